// round 2
// baseline (speedup 1.0000x reference)
#include <cuda_runtime.h>
#include <math.h>

// ---------------- problem dims ----------------
#define BB   8
#define SS   512      // src seq len (== tgt seq len)
#define LL   6
#define HH   8
#define DD   512
#define DKK  64
#define DFF  2048
#define MS   (BB*SS)          // 4096 rows
#define HD   (HH*DKK)         // 512

// ---------------- scratch (device globals; allocation-free) ----------------
__device__ float g_x  [MS*DD];          // encoder activations / enc output
__device__ float g_y  [MS*DD];          // decoder activations
__device__ float g_qkv[MS*3*HD];        // packed QKV (or Q + KV for cross)
__device__ float g_P  [BB*HH*SS*SS];    // attention probs (64 MB)
__device__ float g_ao [MS*DD];          // attn head-concat output
__device__ float g_a  [MS*DD];          // sublayer output (pre-LN)
__device__ float g_ff [MS*DFF];         // FF hidden
__device__ float g_wp [DD*3*HD];        // repacked qkv weights
__device__ float g_bp [3*HD];           // repacked qkv bias
__device__ float g_pe [SS*DD];          // positional encoding table

// ---------------- GEMM ----------------
// C[z] = alpha * A[z] * B[z](^T) + bias ; per-batch offsets split as
// off = (z/zdiv)*s + (z%zdiv)*s2 for A, B, C.
template<int BM,int BN,int BK,int TM,int TN,bool TRANSB>
__global__ __launch_bounds__((BM/TM)*(BN/TN))
void gemm_kernel(const float* __restrict__ A, const float* __restrict__ B,
                 float* __restrict__ C, const float* __restrict__ bias,
                 int K, int lda, int ldb, int ldc,
                 long sA, long sA2, long sB, long sB2, long sC, long sC2, int zdiv,
                 float alpha, int relu)
{
    constexpr int THREADS = (BM/TM)*(BN/TN);
    __shared__ float As[BK][BM+4];
    __shared__ float Bs[BK][BN+4];

    long z  = blockIdx.z;
    long zq = z / zdiv, zr = z % zdiv;
    A += zq*sA + zr*sA2;
    B += zq*sB + zr*sB2;
    C += zq*sC + zr*sC2;

    const int bm = blockIdx.y*BM, bn = blockIdx.x*BN;
    const int tid  = threadIdx.x;
    const int tcol = tid % (BN/TN);
    const int trow = tid / (BN/TN);

    float acc[TM][TN];
    #pragma unroll
    for (int i = 0; i < TM; i++)
        #pragma unroll
        for (int j = 0; j < TN; j++) acc[i][j] = 0.f;

    for (int k0 = 0; k0 < K; k0 += BK) {
        // A tile -> As[k][m] (transposed)
        #pragma unroll
        for (int i = tid; i < BM*BK/4; i += THREADS) {
            int r  = i / (BK/4);
            int c4 = (i % (BK/4))*4;
            float4 v = *(const float4*)(A + (long)(bm+r)*lda + k0 + c4);
            As[c4+0][r] = v.x; As[c4+1][r] = v.y;
            As[c4+2][r] = v.z; As[c4+3][r] = v.w;
        }
        if (!TRANSB) {
            #pragma unroll
            for (int i = tid; i < BK*BN/4; i += THREADS) {
                int r  = i / (BN/4);
                int c4 = (i % (BN/4))*4;
                float4 v = *(const float4*)(B + (long)(k0+r)*ldb + bn + c4);
                *(float4*)&Bs[r][c4] = v;
            }
        } else {
            #pragma unroll
            for (int i = tid; i < BN*BK/4; i += THREADS) {
                int n  = i / (BK/4);
                int c4 = (i % (BK/4))*4;
                float4 v = *(const float4*)(B + (long)(bn+n)*ldb + k0 + c4);
                Bs[c4+0][n] = v.x; Bs[c4+1][n] = v.y;
                Bs[c4+2][n] = v.z; Bs[c4+3][n] = v.w;
            }
        }
        __syncthreads();

        #pragma unroll
        for (int kk = 0; kk < BK; kk++) {
            float a_frag[TM], b_frag[TN];
            #pragma unroll
            for (int i = 0; i < TM; i += 4)
                *(float4*)&a_frag[i] = *(const float4*)&As[kk][trow*TM + i];
            #pragma unroll
            for (int j = 0; j < TN; j += 4)
                *(float4*)&b_frag[j] = *(const float4*)&Bs[kk][tcol*TN + j];
            #pragma unroll
            for (int i = 0; i < TM; i++)
                #pragma unroll
                for (int j = 0; j < TN; j++)
                    acc[i][j] += a_frag[i]*b_frag[j];
        }
        __syncthreads();
    }

    #pragma unroll
    for (int i = 0; i < TM; i++) {
        long r = bm + trow*TM + i;
        #pragma unroll
        for (int j = 0; j < TN; j++) {
            int gn = bn + tcol*TN + j;
            float v = alpha*acc[i][j];
            if (bias) v += bias[gn];
            if (relu) v = fmaxf(v, 0.f);
            C[r*(long)ldc + gn] = v;
        }
    }
}

// ---------------- softmax (exp -> mask -> normalize, max-stabilized) ----------------
__global__ void softmax_kernel(float* __restrict__ P, int Sk, int causal)
{
    int q = blockIdx.x;               // gridDim.x == Sq
    long z = blockIdx.y;
    float* row = P + (z*(long)gridDim.x + q)*(long)Sk;
    int valid = causal ? (q+1) : Sk;
    int tid = threadIdx.x;

    __shared__ float red[256];
    float m = -1e30f;
    for (int i = tid; i < valid; i += 256) m = fmaxf(m, row[i]);
    red[tid] = m; __syncthreads();
    for (int s = 128; s > 0; s >>= 1) { if (tid < s) red[tid] = fmaxf(red[tid], red[tid+s]); __syncthreads(); }
    m = red[0]; __syncthreads();

    float ev[2];
    int cnt = 0;
    float sum = 0.f;
    for (int i = tid; i < Sk; i += 256) {
        float e = (i < valid) ? expf(row[i] - m) : 0.f;
        ev[cnt++] = e;
        sum += e;
    }
    red[tid] = sum; __syncthreads();
    for (int s = 128; s > 0; s >>= 1) { if (tid < s) red[tid] += red[tid+s]; __syncthreads(); }
    float inv = 1.f / red[0];
    cnt = 0;
    for (int i = tid; i < Sk; i += 256) row[i] = ev[cnt++]*inv;
}

// ---------------- residual + LayerNorm ----------------
__global__ void add_ln_kernel(const float* __restrict__ x, const float* __restrict__ a,
                              const float* __restrict__ g, const float* __restrict__ b,
                              float* __restrict__ out)
{
    long row = blockIdx.x;
    int tid = threadIdx.x;
    const float* xr = x + row*DD;
    const float* ar = a + row*DD;
    float v0 = xr[tid]      + ar[tid];
    float v1 = xr[tid+256]  + ar[tid+256];

    __shared__ float red[256];
    red[tid] = v0 + v1; __syncthreads();
    for (int s = 128; s > 0; s >>= 1) { if (tid < s) red[tid] += red[tid+s]; __syncthreads(); }
    float mean = red[0]*(1.f/DD);
    __syncthreads();
    red[tid] = v0*v0 + v1*v1; __syncthreads();
    for (int s = 128; s > 0; s >>= 1) { if (tid < s) red[tid] += red[tid+s]; __syncthreads(); }
    float var = red[0]*(1.f/DD) - mean*mean;
    float rs = rsqrtf(var + 1e-5f);
    out[row*DD + tid]     = (v0-mean)*rs*g[tid]     + b[tid];
    out[row*DD + tid+256] = (v1-mean)*rs*g[tid+256] + b[tid+256];
}

// ---------------- positional encoding ----------------
__global__ void pe_kernel(float* __restrict__ pe)
{
    int idx = blockIdx.x*blockDim.x + threadIdx.x;
    if (idx >= SS*DD) return;
    int d = idx & (DD-1);
    int s = idx >> 9;
    int i = d >> 1;
    double denom = exp(-log(10000.0) * (double)i / 256.0);
    double ang = (double)s * denom;
    pe[idx] = (d & 1) ? (float)cos(ang) : (float)sin(ang);
}

__global__ void add_pe_kernel(const float* __restrict__ src, const float* __restrict__ pe,
                              float* __restrict__ out)
{
    int idx = blockIdx.x*blockDim.x + threadIdx.x;
    if (idx >= MS*DD) return;
    out[idx] = src[idx] + pe[idx & (SS*DD - 1)];
}

// ---------------- weight repack: [P0..P0+NP)[H][D][DK] -> [D][NP*H*DK] ----------------
__global__ void repack_w_kernel(const float* __restrict__ w, float* __restrict__ wp,
                                int P0, int NP)
{
    int n = NP*HD;
    int total = DD*n;
    int idx = blockIdx.x*blockDim.x + threadIdx.x;
    if (idx >= total) return;
    int j = idx % n, d = idx / n;
    int p = j / HD, rem = j % HD;
    int h = rem / DKK, k = rem % DKK;
    wp[idx] = w[(((long)(P0+p)*HH + h)*DD + d)*DKK + k];
}
__global__ void repack_b_kernel(const float* __restrict__ b, float* __restrict__ bp,
                                int P0, int NP)
{
    int n = NP*HD;
    int idx = blockIdx.x*blockDim.x + threadIdx.x;
    if (idx >= n) return;
    int p = idx / HD, rem = idx % HD;
    bp[idx] = b[(P0+p)*HD + rem];
}

// ---------------- host orchestration ----------------
static float *px, *py, *pqkv, *pP, *pao, *pa, *pff, *pwp, *pbp, *ppe;

static void get_ptrs()
{
    if (px) return;
    cudaGetSymbolAddress((void**)&px,  g_x);
    cudaGetSymbolAddress((void**)&py,  g_y);
    cudaGetSymbolAddress((void**)&pqkv,g_qkv);
    cudaGetSymbolAddress((void**)&pP,  g_P);
    cudaGetSymbolAddress((void**)&pao, g_ao);
    cudaGetSymbolAddress((void**)&pa,  g_a);
    cudaGetSymbolAddress((void**)&pff, g_ff);
    cudaGetSymbolAddress((void**)&pwp, g_wp);
    cudaGetSymbolAddress((void**)&pbp, g_bp);
    cudaGetSymbolAddress((void**)&ppe, g_pe);
}

static void launch_gemm(bool small, bool transb,
    const float* A, const float* B, float* C, const float* bias,
    int M, int N, int K, int lda, int ldb, int ldc,
    long sA, long sA2, long sB, long sB2, long sC, long sC2, int zdiv, int batch,
    float alpha, int relu)
{
    if (small) {
        dim3 grid(N/64, M/64, batch);
        gemm_kernel<64,64,16,4,4,false><<<grid,256>>>(A,B,C,bias,K,lda,ldb,ldc,
            sA,sA2,sB,sB2,sC,sC2,zdiv,alpha,relu);
    } else if (transb) {
        dim3 grid(N/128, M/128, batch);
        gemm_kernel<128,128,8,8,8,true><<<grid,256>>>(A,B,C,bias,K,lda,ldb,ldc,
            sA,sA2,sB,sB2,sC,sC2,zdiv,alpha,relu);
    } else {
        dim3 grid(N/128, M/128, batch);
        gemm_kernel<128,128,8,8,8,false><<<grid,256>>>(A,B,C,bias,K,lda,ldb,ldc,
            sA,sA2,sB,sB2,sC,sC2,zdiv,alpha,relu);
    }
}

// full MHA sublayer: result (pre-LN) in g_a
static void attn_block(const float* xq, const float* xkv, bool cross,
                       const float* w, const float* bqkv,
                       const float* wo, const float* bo, int causal)
{
    if (!cross) {
        int n = 3*HD;
        repack_w_kernel<<<(DD*n+255)/256,256>>>(w, pwp, 0, 3);
        repack_b_kernel<<<(n+255)/256,256>>>(bqkv, pbp, 0, 3);
        launch_gemm(false,false, xq, pwp, pqkv, pbp, MS, n, DD, DD, n, n,
                    0,0,0,0,0,0,1,1, 1.f,0);
    } else {
        repack_w_kernel<<<(DD*HD+255)/256,256>>>(w, pwp, 0, 1);
        repack_b_kernel<<<(HD+255)/256,256>>>(bqkv, pbp, 0, 1);
        launch_gemm(false,false, xq, pwp, pqkv, pbp, MS, HD, DD, DD, HD, HD,
                    0,0,0,0,0,0,1,1, 1.f,0);
        repack_w_kernel<<<(DD*2*HD+255)/256,256>>>(w, pwp, 1, 2);
        repack_b_kernel<<<(2*HD+255)/256,256>>>(bqkv, pbp, 1, 2);
        launch_gemm(false,false, xkv, pwp, pqkv + (long)MS*HD, pbp, MS, 2*HD, DD,
                    DD, 2*HD, 2*HD, 0,0,0,0,0,0,1,1, 1.f,0);
    }

    const float *qb, *kb, *vb;
    int qld, kvld;
    if (!cross) { qb = pqkv; qld = 3*HD; kb = pqkv + HD; vb = pqkv + 2*HD; kvld = 3*HD; }
    else        { qb = pqkv; qld = HD;   kb = pqkv + (long)MS*HD; vb = kb + HD; kvld = 2*HD; }

    // logits[b,h,q,s] = (1/8) * Q . K^T     (batched over z = b*H + h)
    launch_gemm(false,true, qb, kb, pP, nullptr,
        SS, SS, DKK, qld, kvld, SS,
        (long)SS*qld, DKK, (long)SS*kvld, DKK,
        (long)HH*SS*SS, (long)SS*SS, HH, BB*HH,
        0.125f, 0);

    softmax_kernel<<<dim3(SS, BB*HH), 256>>>(pP, SS, causal);

    // o[b,h,q,k] = P . V  -> concat-head layout [b*S][H*DK]
    launch_gemm(true,false, pP, vb, pao, nullptr,
        SS, DKK, SS, SS, kvld, HD,
        (long)HH*SS*SS, (long)SS*SS, (long)SS*kvld, DKK,
        (long)SS*HD, DKK, HH, BB*HH,
        1.f, 0);

    // output projection
    launch_gemm(false,false, pao, wo, pa, bo, MS, DD, HD, HD, DD, DD,
                0,0,0,0,0,0,1,1, 1.f,0);
}

static void ffn_block(const float* x, const float* w1, const float* b1,
                      const float* w2, const float* b2)
{
    launch_gemm(false,false, x,   w1, pff, b1, MS, DFF, DD,  DD,  DFF, DFF,
                0,0,0,0,0,0,1,1, 1.f,1);
    launch_gemm(false,false, pff, w2, pa,  b2, MS, DD,  DFF, DFF, DD,  DD,
                0,0,0,0,0,0,1,1, 1.f,0);
}

extern "C" void kernel_launch(void* const* d_in, const int* in_sizes, int n_in,
                              void* d_out, int out_size)
{
    const float* src  = (const float*)d_in[0];
    const float* tgt  = (const float*)d_in[1];
    const float* eaw  = (const float*)d_in[2];
    const float* eab  = (const float*)d_in[3];
    const float* ewo  = (const float*)d_in[4];
    const float* ebo  = (const float*)d_in[5];
    const float* elg  = (const float*)d_in[6];
    const float* elb  = (const float*)d_in[7];
    const float* efw1 = (const float*)d_in[8];
    const float* efb1 = (const float*)d_in[9];
    const float* efw2 = (const float*)d_in[10];
    const float* efb2 = (const float*)d_in[11];
    const float* daw  = (const float*)d_in[12];
    const float* dab  = (const float*)d_in[13];
    const float* dwo  = (const float*)d_in[14];
    const float* dbo  = (const float*)d_in[15];
    const float* dlg  = (const float*)d_in[16];
    const float* dlb  = (const float*)d_in[17];
    const float* dfw1 = (const float*)d_in[18];
    const float* dfb1 = (const float*)d_in[19];
    const float* dfw2 = (const float*)d_in[20];
    const float* dfb2 = (const float*)d_in[21];
    float* out = (float*)d_out;

    get_ptrs();

    pe_kernel<<<(SS*DD+255)/256,256>>>(ppe);
    add_pe_kernel<<<(MS*DD+255)/256,256>>>(src, ppe, px);

    const long WATT = (long)3*HH*DD*DKK;   // 786432: per-(layer[,branch]) attn weight slice
    const long WO_S = (long)HD*DD;         // 262144

    // ---------------- encoder ----------------
    for (int l = 0; l < LL; l++) {
        attn_block(px, px, false,
                   eaw + (long)l*WATT, eab + (long)l*3*HD,
                   ewo + (long)l*WO_S, ebo + (long)l*DD, 0);
        add_ln_kernel<<<MS,256>>>(px, pa, elg + (long)l*2*DD,      elb + (long)l*2*DD,      px);
        ffn_block(px, efw1 + (long)l*DD*DFF, efb1 + (long)l*DFF,
                      efw2 + (long)l*DFF*DD, efb2 + (long)l*DD);
        add_ln_kernel<<<MS,256>>>(px, pa, elg + (long)l*2*DD + DD, elb + (long)l*2*DD + DD, px);
    }

    // ---------------- decoder ----------------
    add_pe_kernel<<<(MS*DD+255)/256,256>>>(tgt, ppe, py);

    for (int l = 0; l < LL; l++) {
        // masked self-attention
        attn_block(py, py, false,
                   daw + (long)(l*2+0)*WATT, dab + (long)(l*2+0)*3*HD,
                   dwo + (long)(l*2+0)*WO_S, dbo + (long)(l*2+0)*DD, 1);
        add_ln_kernel<<<MS,256>>>(py, pa, dlg + (long)l*3*DD,        dlb + (long)l*3*DD,        py);
        // cross-attention (K/V from encoder output)
        attn_block(py, px, true,
                   daw + (long)(l*2+1)*WATT, dab + (long)(l*2+1)*3*HD,
                   dwo + (long)(l*2+1)*WO_S, dbo + (long)(l*2+1)*DD, 0);
        add_ln_kernel<<<MS,256>>>(py, pa, dlg + (long)l*3*DD + DD,   dlb + (long)l*3*DD + DD,   py);
        // feed-forward
        ffn_block(py, dfw1 + (long)l*DD*DFF, dfb1 + (long)l*DFF,
                      dfw2 + (long)l*DFF*DD, dfb2 + (long)l*DD);
        float* yo = (l == LL-1) ? out : py;
        add_ln_kernel<<<MS,256>>>(py, pa, dlg + (long)l*3*DD + 2*DD, dlb + (long)l*3*DD + 2*DD, yo);
    }
}

// round 4
// speedup vs baseline: 2.3182x; 2.3182x over previous
#include <cuda_runtime.h>
#include <cuda_bf16.h>
#include <math.h>
#include <stdint.h>

#define BB   8
#define SS_  512
#define LL   6
#define HH   8
#define DD   512
#define DKK  64
#define DFFN 2048
#define MS   (BB*SS_)
#define HD   (HH*DKK)

typedef __nv_bfloat16 bf16;

// ---------------- scratch ----------------
__device__ __align__(1024) bf16  g_As[(long)MS*6144];
__device__ __align__(1024) bf16  g_Ae[(long)MS*1536];
__device__ __align__(1024) bf16  g_Bs[(long)4*1024*1024];
__device__ __align__(1024) bf16  g_Aq[(long)64*512*192];
__device__ __align__(1024) bf16  g_Bk[(long)64*512*192];
__device__ __align__(1024) bf16  g_Bv[(long)64*64*1536];
__device__ __align__(1024) bf16  g_Ap[(long)64*512*1536];
__device__ __align__(1024) float g_P [(long)64*512*512];
__device__ __align__(1024) float g_qkv[(long)MS*1536];
__device__ __align__(1024) float g_x [MS*DD];
__device__ __align__(1024) float g_y [MS*DD];
__device__ __align__(1024) float g_ao[MS*DD];
__device__ __align__(1024) float g_a [MS*DD];
__device__ __align__(1024) float g_ff[MS*DFFN];
__device__ __align__(1024) float g_pe[SS_*DD];
__device__ __align__(1024) float g_bp[1536];

// ---------------- helpers ----------------
__device__ __forceinline__ uint32_t smem_u32(const void* p) {
    uint32_t a;
    asm("{ .reg .u64 t; cvta.to.shared.u64 t, %1; cvt.u32.u64 %0, t; }" : "=r"(a) : "l"(p));
    return a;
}
#define SW128(o) ((o) ^ (((o) >> 3) & 0x70))

__device__ __forceinline__ void cp_async16(uint32_t daddr, const void* gptr) {
    asm volatile("cp.async.cg.shared.global [%0], [%1], 16;" :: "r"(daddr), "l"(gptr));
}
__device__ __forceinline__ void cp_commit() {
    asm volatile("cp.async.commit_group;" ::: "memory");
}
__device__ __forceinline__ void ldmx4(uint32_t* r, uint32_t addr) {
    asm volatile("ldmatrix.sync.aligned.m8n8.x4.shared.b16 {%0,%1,%2,%3}, [%4];"
                 : "=r"(r[0]), "=r"(r[1]), "=r"(r[2]), "=r"(r[3]) : "r"(addr));
}
__device__ __forceinline__ void mma16816(float* d, const uint32_t* a, const uint32_t* b) {
    asm volatile("mma.sync.aligned.m16n8k16.row.col.f32.bf16.bf16.f32 "
                 "{%0,%1,%2,%3}, {%4,%5,%6,%7}, {%8,%9}, {%0,%1,%2,%3};"
                 : "+f"(d[0]), "+f"(d[1]), "+f"(d[2]), "+f"(d[3])
                 : "r"(a[0]), "r"(a[1]), "r"(a[2]), "r"(a[3]), "r"(b[0]), "r"(b[1]));
}
__device__ __forceinline__ void split2(float v, bf16& hi, bf16& lo) {
    hi = __float2bfloat16(v);
    lo = __float2bfloat16(v - __bfloat162float(hi));
}

// ---------------- mma.sync GEMM: C = A'[M,Kp] * B'[N,Kp]^T (+bias, relu) ----------------
// BM=128, BK=64, 256 threads. Warp grid (128/WM) x (BN/WN).
template<int BN, int WM, int WN>
__global__ __launch_bounds__(256)
void gemm_mma(const bf16* __restrict__ A, const bf16* __restrict__ B,
              float* __restrict__ C, const float* __restrict__ bias,
              int Kp, int ldc,
              long sA, long sA2, long sB, long sB2, long sC, long sC2,
              int zdiv, int relu)
{
    constexpr int BM = 128;
    constexpr int ASTAGE = BM*128;          // bytes per A stage (128B rows)
    constexpr int BSTAGE = BN*128;
    constexpr int STAGE  = ASTAGE + BSTAGE;
    constexpr int MT = WM/16, NT = WN/8;
    constexpr int WCOL = BN/WN;

    extern __shared__ char smraw[];
    char* sm = (char*)(((uintptr_t)smraw + 1023) & ~(uintptr_t)1023);

    const int tid  = threadIdx.x;
    const int wid  = tid >> 5, lane = tid & 31;
    const int wm   = (wid / WCOL) * WM;
    const int wn   = (wid % WCOL) * WN;

    long z  = blockIdx.z;
    long zq = z / zdiv, zr = z % zdiv;
    A += zq*sA + zr*sA2;
    B += zq*sB + zr*sB2;
    C += zq*sC + zr*sC2;
    const long bm = (long)blockIdx.y * BM;
    const long bn = (long)blockIdx.x * BN;
    const bf16* Ag = A + bm*(long)Kp;
    const bf16* Bg = B + bn*(long)Kp;
    const int nc = Kp >> 6;

    float acc[MT][NT][4];
    #pragma unroll
    for (int i = 0; i < MT; i++)
        #pragma unroll
        for (int j = 0; j < NT; j++)
            #pragma unroll
            for (int q = 0; q < 4; q++) acc[i][j][q] = 0.f;

    auto issue = [&](int c) {
        char* sa = sm + (c & 1)*STAGE;
        char* sb = sa + ASTAGE;
        uint32_t sa32 = smem_u32(sa), sb32 = smem_u32(sb);
        #pragma unroll
        for (int p = 0; p < BM/32; p++) {
            int idx = tid + p*256;
            int row = idx >> 3, ch = idx & 7;
            cp_async16(sa32 + SW128((uint32_t)(row*128 + ch*16)),
                       Ag + (long)row*Kp + (long)c*64 + ch*8);
        }
        #pragma unroll
        for (int p = 0; p < BN/32; p++) {
            int idx = tid + p*256;
            int row = idx >> 3, ch = idx & 7;
            cp_async16(sb32 + SW128((uint32_t)(row*128 + ch*16)),
                       Bg + (long)row*Kp + (long)c*64 + ch*8);
        }
        cp_commit();
    };

    issue(0);
    if (nc > 1) issue(1);

    for (int c = 0; c < nc; c++) {
        if (c + 1 < nc) asm volatile("cp.async.wait_group 1;" ::: "memory");
        else            asm volatile("cp.async.wait_group 0;" ::: "memory");
        __syncthreads();

        char* sa = sm + (c & 1)*STAGE;
        char* sb = sa + ASTAGE;
        uint32_t abase = smem_u32(sa), bbase = smem_u32(sb);

        #pragma unroll
        for (int ks = 0; ks < 4; ks++) {
            uint32_t af[MT][4], bfr[NT][2];
            #pragma unroll
            for (int i = 0; i < MT; i++) {
                uint32_t off = (uint32_t)((wm + i*16 + (lane & 15))*128 + ks*32 + (lane >> 4)*16);
                ldmx4(af[i], abase + SW128(off));
            }
            #pragma unroll
            for (int j = 0; j < NT/2; j++) {
                uint32_t off = (uint32_t)((wn + j*16 + (lane & 15))*128 + ks*32 + (lane >> 4)*16);
                uint32_t r[4];
                ldmx4(r, bbase + SW128(off));
                bfr[2*j][0]   = r[0]; bfr[2*j][1]   = r[2];
                bfr[2*j+1][0] = r[1]; bfr[2*j+1][1] = r[3];
            }
            #pragma unroll
            for (int i = 0; i < MT; i++)
                #pragma unroll
                for (int j = 0; j < NT; j++)
                    mma16816(acc[i][j], af[i], bfr[j]);
        }
        __syncthreads();
        if (c + 2 < nc) issue(c + 2);
    }

    // epilogue
    #pragma unroll
    for (int i = 0; i < MT; i++) {
        #pragma unroll
        for (int j = 0; j < NT; j++) {
            long r0  = bm + wm + i*16 + (lane >> 2);
            int  col = (int)bn + wn + j*8 + (lane & 3)*2;
            float2 v0 = make_float2(acc[i][j][0], acc[i][j][1]);
            float2 v1 = make_float2(acc[i][j][2], acc[i][j][3]);
            if (bias) {
                float2 bb = *(const float2*)(bias + col);
                v0.x += bb.x; v0.y += bb.y; v1.x += bb.x; v1.y += bb.y;
            }
            if (relu) {
                v0.x = fmaxf(v0.x, 0.f); v0.y = fmaxf(v0.y, 0.f);
                v1.x = fmaxf(v1.x, 0.f); v1.y = fmaxf(v1.y, 0.f);
            }
            *(float2*)(C + r0*(long)ldc + col)     = v0;
            *(float2*)(C + (r0+8)*(long)ldc + col) = v1;
        }
    }
}

// ---------------- pack kernels ----------------
__global__ void pack_A(const float* __restrict__ src, bf16* __restrict__ out,
                       int K, int kshift, long total)
{
    long idx = (long)blockIdx.x*256 + threadIdx.x;
    if (idx >= total) return;
    int  k = (int)(idx & (K-1));
    long m = idx >> kshift;
    bf16 hi, lo; split2(src[idx], hi, lo);
    long ob = m * (long)(3*K);
    out[ob + k] = hi; out[ob + K + k] = hi; out[ob + 2L*K + k] = lo;
}

__global__ void pack_BT(const float* __restrict__ src, bf16* __restrict__ out,
                        int rows, int cols, int ld, long s1, long s2, int zdiv)
{
    __shared__ float t[32][33];
    long z = blockIdx.z;
    const float* s = src + (z/zdiv)*s1 + (z%zdiv)*s2;
    int k0 = blockIdx.x*32, n0 = blockIdx.y*32;
    int tx = threadIdx.x, ty = threadIdx.y;
    #pragma unroll
    for (int i = 0; i < 32; i += 8)
        t[ty+i][tx] = s[(long)(k0+ty+i)*ld + n0 + tx];
    __syncthreads();
    const long K3 = 3L*rows;
    #pragma unroll
    for (int i = 0; i < 32; i += 8) {
        float v = t[tx][ty+i];
        bf16 hi, lo; split2(v, hi, lo);
        long nrow = z*(long)cols + n0 + ty + i;
        long ob = nrow*K3 + k0 + tx;
        out[ob] = hi; out[ob + rows] = lo; out[ob + 2L*rows] = hi;
    }
}

__global__ void pack_qk(const float* __restrict__ qsrc, int qld, int qoff,
                        const float* __restrict__ ksrc, int kld, int koff,
                        bf16* __restrict__ Aq, bf16* __restrict__ Bk)
{
    long idx = (long)blockIdx.x*256 + threadIdx.x;
    if (idx >= (long)64*512*64) return;
    int kk = (int)(idx & 63);
    int s  = (int)((idx >> 6) & 511);
    int z  = (int)(idx >> 15);
    int b = z >> 3, h = z & 7;
    long srow = (long)(b*512 + s);
    float qv = qsrc[srow*qld + qoff + h*64 + kk] * 0.125f;
    float kv = ksrc[srow*kld + koff + h*64 + kk];
    long ob = ((long)z*512 + s)*192;
    bf16 hi, lo;
    split2(qv, hi, lo); Aq[ob+kk] = hi; Aq[ob+64+kk] = hi; Aq[ob+128+kk] = lo;
    split2(kv, hi, lo); Bk[ob+kk] = hi; Bk[ob+64+kk] = lo; Bk[ob+128+kk] = hi;
}

__global__ void softmax_pack(const float* __restrict__ P, bf16* __restrict__ Ap, int causal)
{
    int q = blockIdx.x;
    long z = blockIdx.y;
    const float* row = P + (z*512 + q)*512L;
    bf16* o = Ap + (z*512 + q)*1536L;
    int valid = causal ? (q+1) : 512;
    int tid = threadIdx.x;
    float a0 = row[tid], a1 = row[tid+256];

    __shared__ float red[256];
    float m = -1e30f;
    if (tid < valid) m = a0;
    if (tid+256 < valid) m = fmaxf(m, a1);
    red[tid] = m; __syncthreads();
    for (int s = 128; s > 0; s >>= 1) { if (tid < s) red[tid] = fmaxf(red[tid], red[tid+s]); __syncthreads(); }
    m = red[0]; __syncthreads();

    float e0 = (tid < valid)     ? expf(a0 - m) : 0.f;
    float e1 = (tid+256 < valid) ? expf(a1 - m) : 0.f;
    red[tid] = e0 + e1; __syncthreads();
    for (int s = 128; s > 0; s >>= 1) { if (tid < s) red[tid] += red[tid+s]; __syncthreads(); }
    float inv = 1.f / red[0];

    bf16 hi, lo;
    split2(e0*inv, hi, lo); o[tid]     = hi; o[512+tid]     = hi; o[1024+tid]     = lo;
    split2(e1*inv, hi, lo); o[tid+256] = hi; o[512+tid+256] = hi; o[1024+tid+256] = lo;
}

__global__ void repack_b(const float* __restrict__ b, float* __restrict__ bp, int P0, int NP)
{
    int n = NP*HD;
    int idx = blockIdx.x*blockDim.x + threadIdx.x;
    if (idx >= n) return;
    int p = idx / HD, rem = idx % HD;
    bp[idx] = b[(P0+p)*HD + rem];
}

// ---------------- elementwise ----------------
__global__ void add_ln_kernel(const float* __restrict__ x, const float* __restrict__ a,
                              const float* __restrict__ g, const float* __restrict__ b,
                              float* __restrict__ out)
{
    long row = blockIdx.x;
    int tid = threadIdx.x;
    const float* xr = x + row*DD;
    const float* ar = a + row*DD;
    float v0 = xr[tid]     + ar[tid];
    float v1 = xr[tid+256] + ar[tid+256];
    __shared__ float red[256];
    red[tid] = v0 + v1; __syncthreads();
    for (int s = 128; s > 0; s >>= 1) { if (tid < s) red[tid] += red[tid+s]; __syncthreads(); }
    float mean = red[0]*(1.f/DD);
    __syncthreads();
    red[tid] = v0*v0 + v1*v1; __syncthreads();
    for (int s = 128; s > 0; s >>= 1) { if (tid < s) red[tid] += red[tid+s]; __syncthreads(); }
    float var = red[0]*(1.f/DD) - mean*mean;
    float rs = rsqrtf(var + 1e-5f);
    out[row*DD + tid]     = (v0-mean)*rs*g[tid]     + b[tid];
    out[row*DD + tid+256] = (v1-mean)*rs*g[tid+256] + b[tid+256];
}

__global__ void pe_kernel(float* __restrict__ pe)
{
    int idx = blockIdx.x*blockDim.x + threadIdx.x;
    if (idx >= SS_*DD) return;
    int d = idx & (DD-1);
    int s = idx >> 9;
    int i = d >> 1;
    double denom = exp(-log(10000.0) * (double)i / 256.0);
    double ang = (double)s * denom;
    pe[idx] = (d & 1) ? (float)cos(ang) : (float)sin(ang);
}

__global__ void add_pe_kernel(const float* __restrict__ src, const float* __restrict__ pe,
                              float* __restrict__ out)
{
    int idx = blockIdx.x*blockDim.x + threadIdx.x;
    if (idx >= MS*DD) return;
    out[idx] = src[idx] + pe[idx & (SS_*DD - 1)];
}

// ---------------- host ----------------
static float *px, *py, *pqkv, *pP, *pao, *pa, *pff, *pbp, *ppe;
static bf16  *pAs, *pAe, *pBs, *pAq, *pBk, *pBv, *pAp;

#define SMEM128 (2*(128*128 + 128*128) + 1024)
#define SMEM64  (2*(128*128 + 64*128) + 1024)

static void get_ptrs()
{
    if (px) return;
    cudaGetSymbolAddress((void**)&px,  g_x);
    cudaGetSymbolAddress((void**)&py,  g_y);
    cudaGetSymbolAddress((void**)&pqkv,g_qkv);
    cudaGetSymbolAddress((void**)&pP,  g_P);
    cudaGetSymbolAddress((void**)&pao, g_ao);
    cudaGetSymbolAddress((void**)&pa,  g_a);
    cudaGetSymbolAddress((void**)&pff, g_ff);
    cudaGetSymbolAddress((void**)&pbp, g_bp);
    cudaGetSymbolAddress((void**)&ppe, g_pe);
    cudaGetSymbolAddress((void**)&pAs, g_As);
    cudaGetSymbolAddress((void**)&pAe, g_Ae);
    cudaGetSymbolAddress((void**)&pBs, g_Bs);
    cudaGetSymbolAddress((void**)&pAq, g_Aq);
    cudaGetSymbolAddress((void**)&pBk, g_Bk);
    cudaGetSymbolAddress((void**)&pBv, g_Bv);
    cudaGetSymbolAddress((void**)&pAp, g_Ap);
    cudaFuncSetAttribute(gemm_mma<128,32,64>, cudaFuncAttributeMaxDynamicSharedMemorySize, SMEM128);
    cudaFuncSetAttribute(gemm_mma<64,16,64>,  cudaFuncAttributeMaxDynamicSharedMemorySize, SMEM64);
}

static void gemm(int BN, const bf16* A, const bf16* B, float* C, const float* bias,
                 int M, int N, int Kp, int ldc,
                 long sA, long sA2, long sB, long sB2, long sC, long sC2,
                 int zdiv, int batch, int relu)
{
    dim3 grid(N/BN, M/128, batch);
    if (BN == 128) {
        gemm_mma<128,32,64><<<grid,256,SMEM128>>>(A,B,C,bias,Kp,ldc,
            sA,sA2,sB,sB2,sC,sC2,zdiv,relu);
    } else {
        gemm_mma<64,16,64><<<grid,256,SMEM64>>>(A,B,C,bias,Kp,ldc,
            sA,sA2,sB,sB2,sC,sC2,zdiv,relu);
    }
}

static void attn_tc(const float* xq, bool cross, const float* w, const float* bqkv,
                    const float* wo, const float* bo, int causal)
{
    if (!cross) {
        pack_BT<<<dim3(16,2,24),dim3(32,8)>>>(w, pBs, 512, 64, 64, (long)512*64, 0, 1);
        repack_b<<<6,256>>>(bqkv, pbp, 0, 3);
        pack_A<<<(int)(((long)MS*512+255)/256),256>>>(xq, pAs, 512, 9, (long)MS*512);
        gemm(128, pAs, pBs, pqkv, pbp, MS, 1536, 1536, 1536, 0,0,0,0,0,0, 1, 1, 0);
        pack_qk<<<(int)(((long)64*512*64+255)/256),256>>>(pqkv,1536,0, pqkv,1536,512, pAq, pBk);
        pack_BT<<<dim3(16,2,64),dim3(32,8)>>>(pqkv+1024, pBv, 512, 64, 1536,
                                              (long)512*1536, 64, 8);
    } else {
        pack_BT<<<dim3(16,2,8),dim3(32,8)>>>(w, pBs, 512, 64, 64, (long)512*64, 0, 1);
        repack_b<<<2,256>>>(bqkv, pbp, 0, 1);
        pack_A<<<(int)(((long)MS*512+255)/256),256>>>(xq, pAs, 512, 9, (long)MS*512);
        gemm(128, pAs, pBs, pqkv, pbp, MS, 512, 1536, 512, 0,0,0,0,0,0, 1, 1, 0);
        pack_BT<<<dim3(16,2,16),dim3(32,8)>>>(w + (long)8*512*64, pBs, 512, 64, 64,
                                              (long)512*64, 0, 1);
        repack_b<<<4,256>>>(bqkv, pbp+512, 1, 2);
        gemm(128, pAe, pBs, pqkv + (long)MS*512, pbp+512, MS, 1024, 1536, 1024,
             0,0,0,0,0,0, 1, 1, 0);
        pack_qk<<<(int)(((long)64*512*64+255)/256),256>>>(pqkv,512,0,
            pqkv+(long)MS*512,1024,0, pAq, pBk);
        pack_BT<<<dim3(16,2,64),dim3(32,8)>>>(pqkv + (long)MS*512 + 512, pBv, 512, 64, 1024,
                                              (long)512*1024, 64, 8);
    }

    // logits (1/8 folded into Q pack): per z=(b,h)
    gemm(128, pAq, pBk, pP, nullptr, 512, 512, 192, 512,
         (long)512*192, 0, (long)512*192, 0, (long)512*512, 0, 1, 64, 0);

    softmax_pack<<<dim3(512,64),256>>>(pP, pAp, causal);

    // O = P' * V'^T -> concat-head [b*512+q][h*64+dk]
    gemm(64, pAp, pBv, pao, nullptr, 512, 64, 1536, 512,
         (long)8*512*1536, (long)512*1536, (long)8*64*1536, (long)64*1536,
         (long)512*512, 64, 8, 64, 0);

    // output projection
    pack_A<<<(int)(((long)MS*512+255)/256),256>>>(pao, pAs, 512, 9, (long)MS*512);
    pack_BT<<<dim3(16,16,1),dim3(32,8)>>>(wo, pBs, 512, 512, 512, 0, 0, 1);
    gemm(128, pAs, pBs, pa, bo, MS, 512, 1536, 512, 0,0,0,0,0,0, 1, 1, 0);
}

static void ffn_tc(const float* x, const float* w1, const float* b1,
                   const float* w2, const float* b2)
{
    pack_A<<<(int)(((long)MS*512+255)/256),256>>>(x, pAs, 512, 9, (long)MS*512);
    pack_BT<<<dim3(16,64,1),dim3(32,8)>>>(w1, pBs, 512, 2048, 2048, 0, 0, 1);
    gemm(128, pAs, pBs, pff, b1, MS, 2048, 1536, 2048, 0,0,0,0,0,0, 1, 1, 1);
    pack_A<<<(int)(((long)MS*2048+255)/256),256>>>(pff, pAs, 2048, 11, (long)MS*2048);
    pack_BT<<<dim3(64,16,1),dim3(32,8)>>>(w2, pBs, 2048, 512, 512, 0, 0, 1);
    gemm(128, pAs, pBs, pa, b2, MS, 512, 6144, 512, 0,0,0,0,0,0, 1, 1, 0);
}

extern "C" void kernel_launch(void* const* d_in, const int* in_sizes, int n_in,
                              void* d_out, int out_size)
{
    const float* src  = (const float*)d_in[0];
    const float* tgt  = (const float*)d_in[1];
    const float* eaw  = (const float*)d_in[2];
    const float* eab  = (const float*)d_in[3];
    const float* ewo  = (const float*)d_in[4];
    const float* ebo  = (const float*)d_in[5];
    const float* elg  = (const float*)d_in[6];
    const float* elb  = (const float*)d_in[7];
    const float* efw1 = (const float*)d_in[8];
    const float* efb1 = (const float*)d_in[9];
    const float* efw2 = (const float*)d_in[10];
    const float* efb2 = (const float*)d_in[11];
    const float* daw  = (const float*)d_in[12];
    const float* dab  = (const float*)d_in[13];
    const float* dwo  = (const float*)d_in[14];
    const float* dbo  = (const float*)d_in[15];
    const float* dlg  = (const float*)d_in[16];
    const float* dlb  = (const float*)d_in[17];
    const float* dfw1 = (const float*)d_in[18];
    const float* dfb1 = (const float*)d_in[19];
    const float* dfw2 = (const float*)d_in[20];
    const float* dfb2 = (const float*)d_in[21];
    float* out = (float*)d_out;

    get_ptrs();

    pe_kernel<<<(SS_*DD+255)/256,256>>>(ppe);
    add_pe_kernel<<<(MS*DD+255)/256,256>>>(src, ppe, px);

    const long WATT = (long)3*HH*DD*DKK;
    const long WO_S = (long)HD*DD;

    for (int l = 0; l < LL; l++) {
        attn_tc(px, false,
                eaw + (long)l*WATT, eab + (long)l*3*HD,
                ewo + (long)l*WO_S, ebo + (long)l*DD, 0);
        add_ln_kernel<<<MS,256>>>(px, pa, elg + (long)l*2*DD,      elb + (long)l*2*DD,      px);
        ffn_tc(px, efw1 + (long)l*DD*DFFN, efb1 + (long)l*DFFN,
                   efw2 + (long)l*DFFN*DD, efb2 + (long)l*DD);
        add_ln_kernel<<<MS,256>>>(px, pa, elg + (long)l*2*DD + DD, elb + (long)l*2*DD + DD, px);
    }

    // cache encoder output split for all cross-attn layers
    pack_A<<<(int)(((long)MS*512+255)/256),256>>>(px, pAe, 512, 9, (long)MS*512);

    add_pe_kernel<<<(MS*DD+255)/256,256>>>(tgt, ppe, py);

    for (int l = 0; l < LL; l++) {
        attn_tc(py, false,
                daw + (long)(l*2+0)*WATT, dab + (long)(l*2+0)*3*HD,
                dwo + (long)(l*2+0)*WO_S, dbo + (long)(l*2+0)*DD, 1);
        add_ln_kernel<<<MS,256>>>(py, pa, dlg + (long)l*3*DD,        dlb + (long)l*3*DD,        py);
        attn_tc(py, true,
                daw + (long)(l*2+1)*WATT, dab + (long)(l*2+1)*3*HD,
                dwo + (long)(l*2+1)*WO_S, dbo + (long)(l*2+1)*DD, 0);
        add_ln_kernel<<<MS,256>>>(py, pa, dlg + (long)l*3*DD + DD,   dlb + (long)l*3*DD + DD,   py);
        ffn_tc(py, dfw1 + (long)l*DD*DFFN, dfb1 + (long)l*DFFN,
                   dfw2 + (long)l*DFFN*DD, dfb2 + (long)l*DD);
        float* yo = (l == LL-1) ? out : py;
        add_ln_kernel<<<MS,256>>>(py, pa, dlg + (long)l*3*DD + 2*DD, dlb + (long)l*3*DD + 2*DD, yo);
    }
}

// round 5
// speedup vs baseline: 2.3388x; 1.0089x over previous
#include <cuda_runtime.h>
#include <cuda_bf16.h>
#include <math.h>
#include <stdint.h>

#define BB   8
#define SS_  512
#define LL   6
#define HH   8
#define DD   512
#define DKK  64
#define DFFN 2048
#define MS   (BB*SS_)
#define HD   (HH*DKK)

typedef __nv_bfloat16 bf16;

// ---------------- scratch ----------------
__device__ __align__(1024) bf16  g_W  [132120576];        // all packed weights (264MB)
__device__ __align__(1024) bf16  g_Ax [(long)MS*1536];    // split of current activations
__device__ __align__(1024) bf16  g_Ae [(long)MS*1536];    // split of encoder output
__device__ __align__(1024) bf16  g_Aff[(long)MS*6144];    // split of FF hidden
__device__ __align__(1024) bf16  g_Ao [(long)MS*1536];    // split of attn head-concat out
__device__ __align__(1024) bf16  g_Aq [(long)64*512*192];
__device__ __align__(1024) bf16  g_Bk [(long)64*512*192];
__device__ __align__(1024) bf16  g_Bv [(long)64*64*1536];
__device__ __align__(1024) bf16  g_Ap [(long)64*512*1536];
__device__ __align__(1024) float g_P  [(long)64*512*512];
__device__ __align__(1024) float g_qkv[(long)MS*1536];
__device__ __align__(1024) float g_x [MS*DD];
__device__ __align__(1024) float g_y [MS*DD];
__device__ __align__(1024) float g_a [MS*DD];
__device__ __align__(1024) float g_pe[SS_*DD];

// ---------------- helpers ----------------
__device__ __forceinline__ uint32_t smem_u32(const void* p) {
    uint32_t a;
    asm("{ .reg .u64 t; cvta.to.shared.u64 t, %1; cvt.u32.u64 %0, t; }" : "=r"(a) : "l"(p));
    return a;
}
#define SW128(o) ((o) ^ (((o) >> 3) & 0x70))

__device__ __forceinline__ void cp_async16(uint32_t daddr, const void* gptr) {
    asm volatile("cp.async.cg.shared.global [%0], [%1], 16;" :: "r"(daddr), "l"(gptr));
}
__device__ __forceinline__ void cp_commit() {
    asm volatile("cp.async.commit_group;" ::: "memory");
}
__device__ __forceinline__ void ldmx4(uint32_t* r, uint32_t addr) {
    asm volatile("ldmatrix.sync.aligned.m8n8.x4.shared.b16 {%0,%1,%2,%3}, [%4];"
                 : "=r"(r[0]), "=r"(r[1]), "=r"(r[2]), "=r"(r[3]) : "r"(addr));
}
__device__ __forceinline__ void mma16816(float* d, const uint32_t* a, const uint32_t* b) {
    asm volatile("mma.sync.aligned.m16n8k16.row.col.f32.bf16.bf16.f32 "
                 "{%0,%1,%2,%3}, {%4,%5,%6,%7}, {%8,%9}, {%0,%1,%2,%3};"
                 : "+f"(d[0]), "+f"(d[1]), "+f"(d[2]), "+f"(d[3])
                 : "r"(a[0]), "r"(a[1]), "r"(a[2]), "r"(a[3]), "r"(b[0]), "r"(b[1]));
}
__device__ __forceinline__ void split2(float v, bf16& hi, bf16& lo) {
    hi = __float2bfloat16(v);
    lo = __float2bfloat16(v - __bfloat162float(hi));
}

// ---------------- GEMM: C = A'[M,Kp] * B'[N,Kp]^T (+bias,relu); optional split bf16 out --------
// BM=128, BK=64 elems, 3 stages, 256 threads.
template<int BN, int WM, int WN>
__global__ __launch_bounds__(256, 2)
void gemm_mma(const bf16* __restrict__ A, const bf16* __restrict__ B,
              float* __restrict__ C, const float* __restrict__ bias,
              bf16* __restrict__ Cs, int nreg,
              int Kp, int ldc,
              long sA, long sA2, long sB, long sB2, long sC, long sC2,
              long sCs, long sCs2,
              int zdiv, int relu)
{
    constexpr int BM = 128;
    constexpr int ASZ = BM*128, BSZ = BN*128, STG = ASZ + BSZ;
    constexpr int MT = WM/16, NT = WN/8, WCOLS = BN/WN;
    const int ldcs = 3*nreg;

    extern __shared__ char smraw[];
    char* sm = (char*)(((uintptr_t)smraw + 1023) & ~(uintptr_t)1023);

    const int tid = threadIdx.x;
    const int wid = tid >> 5, lane = tid & 31;
    const int wm = (wid / WCOLS) * WM;
    const int wn = (wid % WCOLS) * WN;

    long z  = blockIdx.z;
    long zq = z / zdiv, zr = z % zdiv;
    A += zq*sA + zr*sA2;
    B += zq*sB + zr*sB2;
    if (C)  C  += zq*sC  + zr*sC2;
    if (Cs) Cs += zq*sCs + zr*sCs2;
    const long bm = (long)blockIdx.y * BM;
    const long bn = (long)blockIdx.x * BN;
    const bf16* Ag = A + bm*(long)Kp;
    const bf16* Bg = B + bn*(long)Kp;
    const int nc = Kp >> 6;

    float acc[MT][NT][4];
    #pragma unroll
    for (int i = 0; i < MT; i++)
        #pragma unroll
        for (int j = 0; j < NT; j++)
            #pragma unroll
            for (int q = 0; q < 4; q++) acc[i][j][q] = 0.f;

    auto issue = [&](int c) {
        char* sa = sm + (c % 3)*STG;
        char* sb = sa + ASZ;
        uint32_t sa32 = smem_u32(sa), sb32 = smem_u32(sb);
        #pragma unroll
        for (int p = 0; p < BM/32; p++) {
            int idx = tid + p*256;
            int row = idx >> 3, ch = idx & 7;
            cp_async16(sa32 + SW128((uint32_t)(row*128 + ch*16)),
                       Ag + (long)row*Kp + (long)c*64 + ch*8);
        }
        #pragma unroll
        for (int p = 0; p < BN/32; p++) {
            int idx = tid + p*256;
            int row = idx >> 3, ch = idx & 7;
            cp_async16(sb32 + SW128((uint32_t)(row*128 + ch*16)),
                       Bg + (long)row*Kp + (long)c*64 + ch*8);
        }
        cp_commit();
    };

    issue(0);
    if (nc > 1) issue(1);
    if (nc > 2) issue(2);

    for (int c = 0; c < nc; c++) {
        int rem = nc - 1 - c;
        if (rem >= 2)      asm volatile("cp.async.wait_group 2;" ::: "memory");
        else if (rem == 1) asm volatile("cp.async.wait_group 1;" ::: "memory");
        else               asm volatile("cp.async.wait_group 0;" ::: "memory");
        __syncthreads();

        char* sa = sm + (c % 3)*STG;
        char* sb = sa + ASZ;
        uint32_t abase = smem_u32(sa), bbase = smem_u32(sb);

        #pragma unroll
        for (int ks = 0; ks < 4; ks++) {
            uint32_t af[MT][4], bfr[NT][2];
            #pragma unroll
            for (int i = 0; i < MT; i++) {
                uint32_t off = (uint32_t)((wm + i*16 + (lane & 15))*128 + ks*32 + (lane >> 4)*16);
                ldmx4(af[i], abase + SW128(off));
            }
            #pragma unroll
            for (int j = 0; j < NT/2; j++) {
                uint32_t off = (uint32_t)((wn + j*16 + (lane & 15))*128 + ks*32 + (lane >> 4)*16);
                uint32_t r[4];
                ldmx4(r, bbase + SW128(off));
                bfr[2*j][0]   = r[0]; bfr[2*j][1]   = r[2];
                bfr[2*j+1][0] = r[1]; bfr[2*j+1][1] = r[3];
            }
            #pragma unroll
            for (int i = 0; i < MT; i++)
                #pragma unroll
                for (int j = 0; j < NT; j++)
                    mma16816(acc[i][j], af[i], bfr[j]);
        }
        __syncthreads();
        if (c + 3 < nc) issue(c + 3);
    }

    // epilogue
    #pragma unroll
    for (int i = 0; i < MT; i++) {
        #pragma unroll
        for (int j = 0; j < NT; j++) {
            long r0  = bm + wm + i*16 + (lane >> 2);
            int  col = (int)bn + wn + j*8 + (lane & 3)*2;
            float2 v0 = make_float2(acc[i][j][0], acc[i][j][1]);
            float2 v1 = make_float2(acc[i][j][2], acc[i][j][3]);
            if (bias) {
                float2 bb = *(const float2*)(bias + col);
                v0.x += bb.x; v0.y += bb.y; v1.x += bb.x; v1.y += bb.y;
            }
            if (relu) {
                v0.x = fmaxf(v0.x, 0.f); v0.y = fmaxf(v0.y, 0.f);
                v1.x = fmaxf(v1.x, 0.f); v1.y = fmaxf(v1.y, 0.f);
            }
            if (C) {
                *(float2*)(C + r0*(long)ldc + col)     = v0;
                *(float2*)(C + (r0+8)*(long)ldc + col) = v1;
            }
            if (Cs) {
                bf16* p0 = Cs + r0*(long)ldcs + col;
                bf16* p1 = Cs + (r0+8)*(long)ldcs + col;
                __nv_bfloat162 h, l;
                h.x = __float2bfloat16(v0.x);
                h.y = __float2bfloat16(v0.y);
                l.x = __float2bfloat16(v0.x - __bfloat162float(h.x));
                l.y = __float2bfloat16(v0.y - __bfloat162float(h.y));
                *(__nv_bfloat162*)(p0)          = h;
                *(__nv_bfloat162*)(p0 + nreg)   = h;
                *(__nv_bfloat162*)(p0 + 2*nreg) = l;
                h.x = __float2bfloat16(v1.x);
                h.y = __float2bfloat16(v1.y);
                l.x = __float2bfloat16(v1.x - __bfloat162float(h.x));
                l.y = __float2bfloat16(v1.y - __bfloat162float(h.y));
                *(__nv_bfloat162*)(p1)          = h;
                *(__nv_bfloat162*)(p1 + nreg)   = h;
                *(__nv_bfloat162*)(p1 + 2*nreg) = l;
            }
        }
    }
}

// ---------------- pack kernels ----------------
__global__ void pack_BT(const float* __restrict__ src, bf16* __restrict__ out,
                        int rows, int cols, int ld, long s1, long s2, int zdiv)
{
    __shared__ float t[32][33];
    long z = blockIdx.z;
    const float* s = src + (z/zdiv)*s1 + (z%zdiv)*s2;
    int k0 = blockIdx.x*32, n0 = blockIdx.y*32;
    int tx = threadIdx.x, ty = threadIdx.y;
    #pragma unroll
    for (int i = 0; i < 32; i += 8)
        t[ty+i][tx] = s[(long)(k0+ty+i)*ld + n0 + tx];
    __syncthreads();
    const long K3 = 3L*rows;
    #pragma unroll
    for (int i = 0; i < 32; i += 8) {
        float v = t[tx][ty+i];
        bf16 hi, lo; split2(v, hi, lo);
        long nrow = z*(long)cols + n0 + ty + i;
        long ob = nrow*K3 + k0 + tx;
        out[ob] = hi; out[ob + rows] = lo; out[ob + 2L*rows] = hi;
    }
}

__global__ void pack_qk(const float* __restrict__ qsrc, int qld, int qoff,
                        const float* __restrict__ ksrc, int kld, int koff,
                        bf16* __restrict__ Aq, bf16* __restrict__ Bk)
{
    long idx = (long)blockIdx.x*256 + threadIdx.x;
    if (idx >= (long)64*512*64) return;
    int kk = (int)(idx & 63);
    int s  = (int)((idx >> 6) & 511);
    int z  = (int)(idx >> 15);
    int b = z >> 3, h = z & 7;
    long srow = (long)(b*512 + s);
    float qv = qsrc[srow*qld + qoff + h*64 + kk] * 0.125f;
    float kv = ksrc[srow*kld + koff + h*64 + kk];
    long ob = ((long)z*512 + s)*192;
    bf16 hi, lo;
    split2(qv, hi, lo); Aq[ob+kk] = hi; Aq[ob+64+kk] = hi; Aq[ob+128+kk] = lo;
    split2(kv, hi, lo); Bk[ob+kk] = hi; Bk[ob+64+kk] = lo; Bk[ob+128+kk] = hi;
}

__global__ void softmax_pack(const float* __restrict__ P, bf16* __restrict__ Ap, int causal)
{
    int q = blockIdx.x;
    long z = blockIdx.y;
    const float* row = P + (z*512 + q)*512L;
    bf16* o = Ap + (z*512 + q)*1536L;
    int valid = causal ? (q+1) : 512;
    int tid = threadIdx.x;
    float a0 = row[tid], a1 = row[tid+256];

    __shared__ float red[256];
    float m = -1e30f;
    if (tid < valid) m = a0;
    if (tid+256 < valid) m = fmaxf(m, a1);
    red[tid] = m; __syncthreads();
    for (int s = 128; s > 0; s >>= 1) { if (tid < s) red[tid] = fmaxf(red[tid], red[tid+s]); __syncthreads(); }
    m = red[0]; __syncthreads();

    float e0 = (tid < valid)     ? expf(a0 - m) : 0.f;
    float e1 = (tid+256 < valid) ? expf(a1 - m) : 0.f;
    red[tid] = e0 + e1; __syncthreads();
    for (int s = 128; s > 0; s >>= 1) { if (tid < s) red[tid] += red[tid+s]; __syncthreads(); }
    float inv = 1.f / red[0];

    bf16 hi, lo;
    split2(e0*inv, hi, lo); o[tid]     = hi; o[512+tid]     = hi; o[1024+tid]     = lo;
    split2(e1*inv, hi, lo); o[tid+256] = hi; o[512+tid+256] = hi; o[1024+tid+256] = lo;
}

// ---------------- elementwise (fused split producers) ----------------
__global__ void add_ln2(const float* __restrict__ x, const float* __restrict__ a,
                        const float* __restrict__ g, const float* __restrict__ b,
                        float* __restrict__ out, bf16* __restrict__ As)
{
    long row = blockIdx.x;
    int tid = threadIdx.x;
    const float* xr = x + row*DD;
    const float* ar = a + row*DD;
    float v0 = xr[tid]     + ar[tid];
    float v1 = xr[tid+256] + ar[tid+256];
    __shared__ float red[256];
    red[tid] = v0 + v1; __syncthreads();
    for (int s = 128; s > 0; s >>= 1) { if (tid < s) red[tid] += red[tid+s]; __syncthreads(); }
    float mean = red[0]*(1.f/DD);
    __syncthreads();
    red[tid] = v0*v0 + v1*v1; __syncthreads();
    for (int s = 128; s > 0; s >>= 1) { if (tid < s) red[tid] += red[tid+s]; __syncthreads(); }
    float var = red[0]*(1.f/DD) - mean*mean;
    float rs = rsqrtf(var + 1e-5f);
    float o0 = (v0-mean)*rs*g[tid]     + b[tid];
    float o1 = (v1-mean)*rs*g[tid+256] + b[tid+256];
    out[row*DD + tid]     = o0;
    out[row*DD + tid+256] = o1;
    long ob = row*1536;
    bf16 hi, lo;
    split2(o0, hi, lo); As[ob+tid]     = hi; As[ob+512+tid]     = hi; As[ob+1024+tid]     = lo;
    split2(o1, hi, lo); As[ob+tid+256] = hi; As[ob+512+tid+256] = hi; As[ob+1024+tid+256] = lo;
}

__global__ void pe_kernel(float* __restrict__ pe)
{
    int idx = blockIdx.x*blockDim.x + threadIdx.x;
    if (idx >= SS_*DD) return;
    int d = idx & (DD-1);
    int s = idx >> 9;
    int i = d >> 1;
    double denom = exp(-log(10000.0) * (double)i / 256.0);
    double ang = (double)s * denom;
    pe[idx] = (d & 1) ? (float)cos(ang) : (float)sin(ang);
}

__global__ void add_pe2(const float* __restrict__ src, const float* __restrict__ pe,
                        float* __restrict__ out, bf16* __restrict__ As)
{
    int idx = blockIdx.x*blockDim.x + threadIdx.x;
    if (idx >= MS*DD) return;
    float v = src[idx] + pe[idx & (SS_*DD - 1)];
    out[idx] = v;
    int c = idx & 511;
    long row = idx >> 9;
    long ob = row*1536;
    bf16 hi, lo; split2(v, hi, lo);
    As[ob+c] = hi; As[ob+512+c] = hi; As[ob+1024+c] = lo;
}

// ---------------- host ----------------
static float *px, *py, *pqkv, *pP, *pa, *ppe;
static bf16  *pW, *pAx, *pAe, *pAff, *pAo, *pAq, *pBk, *pBv, *pAp;

#define SM128 (3*(128*128 + 128*128) + 1024)
#define SM64  (3*(128*128 + 64*128) + 1024)

// packed weight slice sizes (bf16 elems)
#define SZ_QKV (1536L*1536)
#define SZ_WO  (512L*1536)
#define SZ_W1  (2048L*1536)
#define SZ_W2  (512L*6144)
#define SZ_QW  (512L*1536)
#define SZ_KVW (1024L*1536)
#define L_ENC  (SZ_QKV + SZ_WO + SZ_W1 + SZ_W2)
#define L_DEC  (SZ_QKV + SZ_WO + SZ_QW + SZ_KVW + SZ_WO + SZ_W1 + SZ_W2)
#define DEC_BASE (6*L_ENC)

static void get_ptrs()
{
    if (px) return;
    cudaGetSymbolAddress((void**)&px,  g_x);
    cudaGetSymbolAddress((void**)&py,  g_y);
    cudaGetSymbolAddress((void**)&pqkv,g_qkv);
    cudaGetSymbolAddress((void**)&pP,  g_P);
    cudaGetSymbolAddress((void**)&pa,  g_a);
    cudaGetSymbolAddress((void**)&ppe, g_pe);
    cudaGetSymbolAddress((void**)&pW,  g_W);
    cudaGetSymbolAddress((void**)&pAx, g_Ax);
    cudaGetSymbolAddress((void**)&pAe, g_Ae);
    cudaGetSymbolAddress((void**)&pAff,g_Aff);
    cudaGetSymbolAddress((void**)&pAo, g_Ao);
    cudaGetSymbolAddress((void**)&pAq, g_Aq);
    cudaGetSymbolAddress((void**)&pBk, g_Bk);
    cudaGetSymbolAddress((void**)&pBv, g_Bv);
    cudaGetSymbolAddress((void**)&pAp, g_Ap);
    cudaFuncSetAttribute(gemm_mma<128,64,32>, cudaFuncAttributeMaxDynamicSharedMemorySize, SM128);
    cudaFuncSetAttribute(gemm_mma<64,16,64>,  cudaFuncAttributeMaxDynamicSharedMemorySize, SM64);
}

static void gemm128(const bf16* A, const bf16* B, float* C, const float* bias,
                    bf16* Cs, int nreg, int M, int N, int Kp, int ldc,
                    long sA, long sA2, long sB, long sB2, long sC, long sC2,
                    long sCs, long sCs2, int zdiv, int batch, int relu)
{
    dim3 grid(N/128, M/128, batch);
    gemm_mma<128,64,32><<<grid,256,SM128>>>(A,B,C,bias,Cs,nreg,Kp,ldc,
        sA,sA2,sB,sB2,sC,sC2,sCs,sCs2,zdiv,relu);
}
static void gemm64(const bf16* A, const bf16* B, float* C, const float* bias,
                   bf16* Cs, int nreg, int M, int N, int Kp, int ldc,
                   long sA, long sA2, long sB, long sB2, long sC, long sC2,
                   long sCs, long sCs2, int zdiv, int batch, int relu)
{
    dim3 grid(N/64, M/128, batch);
    gemm_mma<64,16,64><<<grid,256,SM64>>>(A,B,C,bias,Cs,nreg,Kp,ldc,
        sA,sA2,sB,sB2,sC,sC2,sCs,sCs2,zdiv,relu);
}

// attention core: Q/K/V already in pqkv. Writes pre-LN attn result to g_a.
static void attn_core(int qld, int qoff, const float* kvsrc, int kvld,
                      const bf16* Wo, const float* bo, int causal)
{
    pack_qk<<<(int)(((long)64*512*64+255)/256),256>>>(pqkv, qld, qoff,
                                                      kvsrc, kvld, 0, pAq, pBk);
    // V pack: kvsrc cols [kvld-1024+512 .. ) ... caller passes kvsrc pointing at K base; V at +512
    pack_BT<<<dim3(16,2,64),dim3(32,8)>>>(kvsrc + 512, pBv, 512, 64, kvld,
                                          (long)512*kvld, 64, 8);
    gemm128(pAq, pBk, pP, nullptr, nullptr, 0, 512, 512, 192, 512,
            (long)512*192, 0, (long)512*192, 0, (long)512*512, 0, 0, 0, 1, 64, 0);
    softmax_pack<<<dim3(512,64),256>>>(pP, pAp, causal);
    gemm64(pAp, pBv, nullptr, nullptr, pAo, 512, 512, 64, 1536, 512,
           (long)8*512*1536, (long)512*1536, (long)8*64*1536, (long)64*1536,
           0, 0, (long)512*1536, 64, 8, 64, 0);
    gemm128(pAo, Wo, pa, bo, nullptr, 0, MS, 512, 1536, 512,
            0,0,0,0,0,0,0,0, 1, 1, 0);
}

extern "C" void kernel_launch(void* const* d_in, const int* in_sizes, int n_in,
                              void* d_out, int out_size)
{
    const float* src  = (const float*)d_in[0];
    const float* tgt  = (const float*)d_in[1];
    const float* eaw  = (const float*)d_in[2];
    const float* eab  = (const float*)d_in[3];
    const float* ewo  = (const float*)d_in[4];
    const float* ebo  = (const float*)d_in[5];
    const float* elg  = (const float*)d_in[6];
    const float* elb  = (const float*)d_in[7];
    const float* efw1 = (const float*)d_in[8];
    const float* efb1 = (const float*)d_in[9];
    const float* efw2 = (const float*)d_in[10];
    const float* efb2 = (const float*)d_in[11];
    const float* daw  = (const float*)d_in[12];
    const float* dab  = (const float*)d_in[13];
    const float* dwo  = (const float*)d_in[14];
    const float* dbo  = (const float*)d_in[15];
    const float* dlg  = (const float*)d_in[16];
    const float* dlb  = (const float*)d_in[17];
    const float* dfw1 = (const float*)d_in[18];
    const float* dfb1 = (const float*)d_in[19];
    const float* dfw2 = (const float*)d_in[20];
    const float* dfb2 = (const float*)d_in[21];
    float* out = (float*)d_out;

    get_ptrs();

    const long WATT = (long)3*HH*DD*DKK;   // 786432
    const long WO_S = (long)HD*DD;

    // -------- pre-pack all weights --------
    for (int l = 0; l < LL; l++) {
        bf16* base = pW + (long)l*L_ENC;
        pack_BT<<<dim3(16,2,24),dim3(32,8)>>>(eaw + (long)l*WATT, base, 512, 64, 64,
                                              (long)512*64, 0, 1);
        pack_BT<<<dim3(16,16,1),dim3(32,8)>>>(ewo + (long)l*WO_S, base + SZ_QKV,
                                              512, 512, 512, 0, 0, 1);
        pack_BT<<<dim3(16,64,1),dim3(32,8)>>>(efw1 + (long)l*DD*DFFN, base + SZ_QKV + SZ_WO,
                                              512, 2048, 2048, 0, 0, 1);
        pack_BT<<<dim3(64,16,1),dim3(32,8)>>>(efw2 + (long)l*DFFN*DD,
                                              base + SZ_QKV + SZ_WO + SZ_W1,
                                              2048, 512, 512, 0, 0, 1);
    }
    for (int l = 0; l < LL; l++) {
        bf16* base = pW + DEC_BASE + (long)l*L_DEC;
        pack_BT<<<dim3(16,2,24),dim3(32,8)>>>(daw + (long)(l*2)*WATT, base, 512, 64, 64,
                                              (long)512*64, 0, 1);
        pack_BT<<<dim3(16,16,1),dim3(32,8)>>>(dwo + (long)(l*2)*WO_S, base + SZ_QKV,
                                              512, 512, 512, 0, 0, 1);
        pack_BT<<<dim3(16,2,8),dim3(32,8)>>>(daw + (long)(l*2+1)*WATT,
                                             base + SZ_QKV + SZ_WO, 512, 64, 64,
                                             (long)512*64, 0, 1);
        pack_BT<<<dim3(16,2,16),dim3(32,8)>>>(daw + (long)(l*2+1)*WATT + (long)8*512*64,
                                              base + SZ_QKV + SZ_WO + SZ_QW, 512, 64, 64,
                                              (long)512*64, 0, 1);
        pack_BT<<<dim3(16,16,1),dim3(32,8)>>>(dwo + (long)(l*2+1)*WO_S,
                                              base + SZ_QKV + SZ_WO + SZ_QW + SZ_KVW,
                                              512, 512, 512, 0, 0, 1);
        pack_BT<<<dim3(16,64,1),dim3(32,8)>>>(dfw1 + (long)l*DD*DFFN,
                                              base + SZ_QKV + 2*SZ_WO + SZ_QW + SZ_KVW,
                                              512, 2048, 2048, 0, 0, 1);
        pack_BT<<<dim3(64,16,1),dim3(32,8)>>>(dfw2 + (long)l*DFFN*DD,
                                              base + SZ_QKV + 2*SZ_WO + SZ_QW + SZ_KVW + SZ_W1,
                                              2048, 512, 512, 0, 0, 1);
    }

    pe_kernel<<<(SS_*DD+255)/256,256>>>(ppe);
    add_pe2<<<(MS*DD+255)/256,256>>>(src, ppe, px, pAx);

    // -------- encoder --------
    for (int l = 0; l < LL; l++) {
        bf16* base = pW + (long)l*L_ENC;
        gemm128(pAx, base, pqkv, eab + (long)l*1536, nullptr, 0,
                MS, 1536, 1536, 1536, 0,0,0,0,0,0,0,0, 1, 1, 0);
        attn_core(1536, 0, pqkv + 512, 1536,
                  base + SZ_QKV, ebo + (long)l*DD, 0);
        add_ln2<<<MS,256>>>(px, pa, elg + (long)l*2*DD, elb + (long)l*2*DD, px, pAx);
        gemm128(pAx, base + SZ_QKV + SZ_WO, nullptr, efb1 + (long)l*DFFN, pAff, 2048,
                MS, 2048, 1536, 2048, 0,0,0,0,0,0,0,0, 1, 1, 1);
        gemm128(pAff, base + SZ_QKV + SZ_WO + SZ_W1, pa, efb2 + (long)l*DD, nullptr, 0,
                MS, 512, 6144, 512, 0,0,0,0,0,0,0,0, 1, 1, 0);
        bf16* As2 = (l == LL-1) ? pAe : pAx;
        add_ln2<<<MS,256>>>(px, pa, elg + (long)l*2*DD + DD, elb + (long)l*2*DD + DD, px, As2);
    }

    // -------- decoder --------
    add_pe2<<<(MS*DD+255)/256,256>>>(tgt, ppe, py, pAx);

    for (int l = 0; l < LL; l++) {
        bf16* base = pW + DEC_BASE + (long)l*L_DEC;
        // masked self-attention
        gemm128(pAx, base, pqkv, dab + (long)(l*2)*1536, nullptr, 0,
                MS, 1536, 1536, 1536, 0,0,0,0,0,0,0,0, 1, 1, 0);
        attn_core(1536, 0, pqkv + 512, 1536,
                  base + SZ_QKV, dbo + (long)(l*2)*DD, 1);
        add_ln2<<<MS,256>>>(py, pa, dlg + (long)l*3*DD, dlb + (long)l*3*DD, py, pAx);
        // cross-attention
        gemm128(pAx, base + SZ_QKV + SZ_WO, pqkv, dab + (long)(l*2+1)*1536, nullptr, 0,
                MS, 512, 1536, 512, 0,0,0,0,0,0,0,0, 1, 1, 0);
        gemm128(pAe, base + SZ_QKV + SZ_WO + SZ_QW, pqkv + (long)MS*512,
                dab + (long)(l*2+1)*1536 + 512, nullptr, 0,
                MS, 1024, 1536, 1024, 0,0,0,0,0,0,0,0, 1, 1, 0);
        attn_core(512, 0, pqkv + (long)MS*512, 1024,
                  base + SZ_QKV + SZ_WO + SZ_QW + SZ_KVW, dbo + (long)(l*2+1)*DD, 0);
        add_ln2<<<MS,256>>>(py, pa, dlg + (long)l*3*DD + DD, dlb + (long)l*3*DD + DD, py, pAx);
        // feed-forward
        gemm128(pAx, base + SZ_QKV + 2*SZ_WO + SZ_QW + SZ_KVW, nullptr,
                dfb1 + (long)l*DFFN, pAff, 2048,
                MS, 2048, 1536, 2048, 0,0,0,0,0,0,0,0, 1, 1, 1);
        gemm128(pAff, base + SZ_QKV + 2*SZ_WO + SZ_QW + SZ_KVW + SZ_W1, pa,
                dfb2 + (long)l*DD, nullptr, 0,
                MS, 512, 6144, 512, 0,0,0,0,0,0,0,0, 1, 1, 0);
        float* yo = (l == LL-1) ? out : py;
        add_ln2<<<MS,256>>>(py, pa, dlg + (long)l*3*DD + 2*DD, dlb + (long)l*3*DD + 2*DD, yo, pAx);
    }
}

// round 6
// speedup vs baseline: 2.7581x; 1.1793x over previous
#include <cuda_runtime.h>
#include <cuda_bf16.h>
#include <math.h>
#include <stdint.h>

#define BB   8
#define SS_  512
#define LL   6
#define HH   8
#define DD   512
#define DKK  64
#define DFFN 2048
#define MS   (BB*SS_)
#define HD   (HH*DKK)

typedef __nv_bfloat16 bf16;

// ---------------- scratch ----------------
__device__ __align__(1024) bf16  g_W  [132120576];
__device__ __align__(1024) bf16  g_Ax [(long)MS*1536];
__device__ __align__(1024) bf16  g_Ae [(long)MS*1536];
__device__ __align__(1024) bf16  g_Aff[(long)MS*6144];
__device__ __align__(1024) bf16  g_Ao [(long)MS*1536];
__device__ __align__(1024) bf16  g_Aq [(long)64*512*192];
__device__ __align__(1024) bf16  g_Bk [(long)64*512*192];
__device__ __align__(1024) bf16  g_Bv [(long)64*64*1536];
__device__ __align__(1024) float g_qkv[(long)MS*1536];
__device__ __align__(1024) float g_x [MS*DD];
__device__ __align__(1024) float g_y [MS*DD];
__device__ __align__(1024) float g_a [MS*DD];
__device__ __align__(1024) float g_pe[SS_*DD];

// ---------------- helpers ----------------
__device__ __forceinline__ uint32_t smem_u32(const void* p) {
    uint32_t a;
    asm("{ .reg .u64 t; cvta.to.shared.u64 t, %1; cvt.u32.u64 %0, t; }" : "=r"(a) : "l"(p));
    return a;
}
#define SW128(o) ((o) ^ (((o) >> 3) & 0x70))

__device__ __forceinline__ void cp_async16(uint32_t daddr, const void* gptr) {
    asm volatile("cp.async.cg.shared.global [%0], [%1], 16;" :: "r"(daddr), "l"(gptr));
}
__device__ __forceinline__ void cp_commit() {
    asm volatile("cp.async.commit_group;" ::: "memory");
}
__device__ __forceinline__ void ldmx4(uint32_t* r, uint32_t addr) {
    asm volatile("ldmatrix.sync.aligned.m8n8.x4.shared.b16 {%0,%1,%2,%3}, [%4];"
                 : "=r"(r[0]), "=r"(r[1]), "=r"(r[2]), "=r"(r[3]) : "r"(addr));
}
__device__ __forceinline__ void mma16816(float* d, const uint32_t* a, const uint32_t* b) {
    asm volatile("mma.sync.aligned.m16n8k16.row.col.f32.bf16.bf16.f32 "
                 "{%0,%1,%2,%3}, {%4,%5,%6,%7}, {%8,%9}, {%0,%1,%2,%3};"
                 : "+f"(d[0]), "+f"(d[1]), "+f"(d[2]), "+f"(d[3])
                 : "r"(a[0]), "r"(a[1]), "r"(a[2]), "r"(a[3]), "r"(b[0]), "r"(b[1]));
}
__device__ __forceinline__ void split2(float v, bf16& hi, bf16& lo) {
    hi = __float2bfloat16(v);
    lo = __float2bfloat16(v - __bfloat162float(hi));
}
// pack two floats' bf16 hi parts into one reg; return residuals
__device__ __forceinline__ uint32_t pack_hi2(float a, float b, float& ra, float& rb) {
    __nv_bfloat162 h;
    h.x = __float2bfloat16(a); h.y = __float2bfloat16(b);
    ra = a - __bfloat162float(h.x);
    rb = b - __bfloat162float(h.y);
    return *(uint32_t*)&h;
}
__device__ __forceinline__ uint32_t pack_bf2(float a, float b) {
    __nv_bfloat162 h;
    h.x = __float2bfloat16(a); h.y = __float2bfloat16(b);
    return *(uint32_t*)&h;
}

// ---------------- GEMM: C = A'[M,Kp] * B'[N,Kp]^T (+bias,relu); optional split out ------------
template<int BN, int WM, int WN>
__global__ __launch_bounds__(256, (BN >= 256 ? 1 : 2))
void gemm_mma(const bf16* __restrict__ A, const bf16* __restrict__ B,
              float* __restrict__ C, const float* __restrict__ bias,
              bf16* __restrict__ Cs, int nreg,
              int Kp, int ldc, int relu)
{
    constexpr int BM = 128;
    constexpr int ASZ = BM*128, BSZ = BN*128, STG = ASZ + BSZ;
    constexpr int MT = WM/16, NT = WN/8, WCOLS = BN/WN;
    const int ldcs = 3*nreg;

    extern __shared__ char smraw[];
    char* sm = (char*)(((uintptr_t)smraw + 1023) & ~(uintptr_t)1023);

    const int tid = threadIdx.x;
    const int wid = tid >> 5, lane = tid & 31;
    const int wm = (wid / WCOLS) * WM;
    const int wn = (wid % WCOLS) * WN;

    const long bm = (long)blockIdx.y * BM;
    const long bn = (long)blockIdx.x * BN;
    const bf16* Ag = A + bm*(long)Kp;
    const bf16* Bg = B + bn*(long)Kp;
    const int nc = Kp >> 6;

    float acc[MT][NT][4];
    #pragma unroll
    for (int i = 0; i < MT; i++)
        #pragma unroll
        for (int j = 0; j < NT; j++)
            #pragma unroll
            for (int q = 0; q < 4; q++) acc[i][j][q] = 0.f;

    auto issue = [&](int c) {
        char* sa = sm + (c % 3)*STG;
        char* sb = sa + ASZ;
        uint32_t sa32 = smem_u32(sa), sb32 = smem_u32(sb);
        #pragma unroll
        for (int p = 0; p < BM/32; p++) {
            int idx = tid + p*256;
            int row = idx >> 3, ch = idx & 7;
            cp_async16(sa32 + SW128((uint32_t)(row*128 + ch*16)),
                       Ag + (long)row*Kp + (long)c*64 + ch*8);
        }
        #pragma unroll
        for (int p = 0; p < BN/32; p++) {
            int idx = tid + p*256;
            int row = idx >> 3, ch = idx & 7;
            cp_async16(sb32 + SW128((uint32_t)(row*128 + ch*16)),
                       Bg + (long)row*Kp + (long)c*64 + ch*8);
        }
        cp_commit();
    };

    issue(0);
    if (nc > 1) issue(1);
    if (nc > 2) issue(2);

    for (int c = 0; c < nc; c++) {
        int rem = nc - 1 - c;
        if (rem >= 2)      asm volatile("cp.async.wait_group 2;" ::: "memory");
        else if (rem == 1) asm volatile("cp.async.wait_group 1;" ::: "memory");
        else               asm volatile("cp.async.wait_group 0;" ::: "memory");
        __syncthreads();

        char* sa = sm + (c % 3)*STG;
        char* sb = sa + ASZ;
        uint32_t abase = smem_u32(sa), bbase = smem_u32(sb);

        #pragma unroll
        for (int ks = 0; ks < 4; ks++) {
            uint32_t af[MT][4], bfr[NT][2];
            #pragma unroll
            for (int i = 0; i < MT; i++) {
                uint32_t off = (uint32_t)((wm + i*16 + (lane & 15))*128 + ks*32 + (lane >> 4)*16);
                ldmx4(af[i], abase + SW128(off));
            }
            #pragma unroll
            for (int j = 0; j < NT/2; j++) {
                uint32_t off = (uint32_t)((wn + j*16 + (lane & 15))*128 + ks*32 + (lane >> 4)*16);
                uint32_t r[4];
                ldmx4(r, bbase + SW128(off));
                bfr[2*j][0]   = r[0]; bfr[2*j][1]   = r[2];
                bfr[2*j+1][0] = r[1]; bfr[2*j+1][1] = r[3];
            }
            #pragma unroll
            for (int i = 0; i < MT; i++)
                #pragma unroll
                for (int j = 0; j < NT; j++)
                    mma16816(acc[i][j], af[i], bfr[j]);
        }
        __syncthreads();
        if (c + 3 < nc) issue(c + 3);
    }

    #pragma unroll
    for (int i = 0; i < MT; i++) {
        #pragma unroll
        for (int j = 0; j < NT; j++) {
            long r0  = bm + wm + i*16 + (lane >> 2);
            int  col = (int)bn + wn + j*8 + (lane & 3)*2;
            float2 v0 = make_float2(acc[i][j][0], acc[i][j][1]);
            float2 v1 = make_float2(acc[i][j][2], acc[i][j][3]);
            if (bias) {
                float2 bb = *(const float2*)(bias + col);
                v0.x += bb.x; v0.y += bb.y; v1.x += bb.x; v1.y += bb.y;
            }
            if (relu) {
                v0.x = fmaxf(v0.x, 0.f); v0.y = fmaxf(v0.y, 0.f);
                v1.x = fmaxf(v1.x, 0.f); v1.y = fmaxf(v1.y, 0.f);
            }
            if (C) {
                *(float2*)(C + r0*(long)ldc + col)     = v0;
                *(float2*)(C + (r0+8)*(long)ldc + col) = v1;
            }
            if (Cs) {
                bf16* p0 = Cs + r0*(long)ldcs + col;
                bf16* p1 = Cs + (r0+8)*(long)ldcs + col;
                __nv_bfloat162 h, l;
                h.x = __float2bfloat16(v0.x);
                h.y = __float2bfloat16(v0.y);
                l.x = __float2bfloat16(v0.x - __bfloat162float(h.x));
                l.y = __float2bfloat16(v0.y - __bfloat162float(h.y));
                *(__nv_bfloat162*)(p0)          = h;
                *(__nv_bfloat162*)(p0 + nreg)   = h;
                *(__nv_bfloat162*)(p0 + 2*nreg) = l;
                h.x = __float2bfloat16(v1.x);
                h.y = __float2bfloat16(v1.y);
                l.x = __float2bfloat16(v1.x - __bfloat162float(h.x));
                l.y = __float2bfloat16(v1.y - __bfloat162float(h.y));
                *(__nv_bfloat162*)(p1)          = h;
                *(__nv_bfloat162*)(p1 + nreg)   = h;
                *(__nv_bfloat162*)(p1 + 2*nreg) = l;
            }
        }
    }
}

// ---------------- fused flash attention ----------------
// grid (4 qtiles, 64 bh), 256 threads. Q' [z][512][192] (pre-scaled), K' [z][512][192],
// V'^T rows (z*64+dk) x [Vh512|Vl512|Vh512]. Output: Ao split rows b*512+q, cols h*64+dk.
__global__ __launch_bounds__(256, 1)
void flash_attn(const bf16* __restrict__ Aq, const bf16* __restrict__ Bk,
                const bf16* __restrict__ Bv, bf16* __restrict__ Ao, int causal)
{
    extern __shared__ char smraw[];
    uint32_t smQ = (smem_u32(smraw) + 1023) & ~1023u;
    uint32_t smK = smQ + 49152;       // 2 stages x 24KB
    uint32_t smV = smQ + 49152 + 49152; // 2 stages x 16KB

    const int tid = threadIdx.x, wid = tid >> 5, lane = tid & 31;
    const int qt = blockIdx.x, z = blockIdx.y;
    const int qbase = qt*128;
    const int nt = causal ? (2*qt + 2) : 8;

    // ---- load Q (once) ----
    {
        const bf16* qsrc = Aq + ((long)z*512 + qbase)*192;
        for (int i = tid; i < 3072; i += 256) {
            int ch = i >> 10, rem = i & 1023;
            int row = rem >> 3, seg = rem & 7;
            cp_async16(smQ + ch*16384 + SW128((uint32_t)(row*128 + seg*16)),
                       qsrc + (long)row*192 + ch*64 + seg*8);
        }
    }
    auto load_kv = [&](int t, int st) {
        uint32_t kst = smK + st*24576;
        uint32_t vst = smV + st*16384;
        const bf16* ksrc = Bk + ((long)z*512 + t*64)*192;
        for (int i = tid; i < 1536; i += 256) {
            int ch = i >> 9, rem = i & 511;
            int row = rem >> 3, seg = rem & 7;
            cp_async16(kst + ch*8192 + SW128((uint32_t)(row*128 + seg*16)),
                       ksrc + (long)row*192 + ch*64 + seg*8);
        }
        const bf16* vsrc = Bv + (long)z*64*1536;
        for (int i = tid; i < 1024; i += 256) {
            int hl = i >> 9, rem = i & 511;
            int dk = rem >> 3, seg = rem & 7;
            cp_async16(vst + hl*8192 + SW128((uint32_t)(dk*128 + seg*16)),
                       vsrc + (long)dk*1536 + hl*512 + t*64 + seg*8);
        }
    };

    load_kv(0, 0); cp_commit();               // group 0: Q + tile0
    if (nt > 1) { load_kv(1, 1); cp_commit(); } // group 1: tile1

    float m0 = -1e30f, m1 = -1e30f, l0 = 0.f, l1 = 0.f;
    float o[8][4];
    #pragma unroll
    for (int j = 0; j < 8; j++)
        #pragma unroll
        for (int q = 0; q < 4; q++) o[j][q] = 0.f;

    const int r0g = qbase + wid*16 + (lane >> 2);
    const int r1g = r0g + 8;

    for (int t = 0; t < nt; t++) {
        if (t + 1 < nt) asm volatile("cp.async.wait_group 1;" ::: "memory");
        else            asm volatile("cp.async.wait_group 0;" ::: "memory");
        __syncthreads();

        uint32_t kst = smK + (t & 1)*24576;
        uint32_t vst = smV + (t & 1)*16384;

        // S = Q' K'^T  (warp: 16 q-rows x 64 kv)
        float sf[8][4];
        #pragma unroll
        for (int j = 0; j < 8; j++)
            #pragma unroll
            for (int q = 0; q < 4; q++) sf[j][q] = 0.f;

        #pragma unroll
        for (int kc = 0; kc < 12; kc++) {
            uint32_t af[4];
            ldmx4(af, smQ + (kc >> 2)*16384 +
                  SW128((uint32_t)((wid*16 + (lane & 15))*128 + (kc & 3)*32 + (lane >> 4)*16)));
            #pragma unroll
            for (int j = 0; j < 4; j++) {
                uint32_t r[4];
                ldmx4(r, kst + (kc >> 2)*8192 +
                      SW128((uint32_t)((j*16 + (lane & 15))*128 + (kc & 3)*32 + (lane >> 4)*16)));
                uint32_t b0[2] = {r[0], r[2]}, b1[2] = {r[1], r[3]};
                mma16816(sf[2*j],   af, b0);
                mma16816(sf[2*j+1], af, b1);
            }
        }

        // causal mask
        if (causal) {
            #pragma unroll
            for (int j = 0; j < 8; j++) {
                int c0 = t*64 + j*8 + (lane & 3)*2;
                if (c0     > r0g) sf[j][0] = -1e30f;
                if (c0 + 1 > r0g) sf[j][1] = -1e30f;
                if (c0     > r1g) sf[j][2] = -1e30f;
                if (c0 + 1 > r1g) sf[j][3] = -1e30f;
            }
        }

        // online softmax
        float tm0 = -1e30f, tm1 = -1e30f;
        #pragma unroll
        for (int j = 0; j < 8; j++) {
            tm0 = fmaxf(tm0, fmaxf(sf[j][0], sf[j][1]));
            tm1 = fmaxf(tm1, fmaxf(sf[j][2], sf[j][3]));
        }
        tm0 = fmaxf(tm0, __shfl_xor_sync(0xffffffffu, tm0, 1));
        tm0 = fmaxf(tm0, __shfl_xor_sync(0xffffffffu, tm0, 2));
        tm1 = fmaxf(tm1, __shfl_xor_sync(0xffffffffu, tm1, 1));
        tm1 = fmaxf(tm1, __shfl_xor_sync(0xffffffffu, tm1, 2));
        float mn0 = fmaxf(m0, tm0), mn1 = fmaxf(m1, tm1);
        float al0 = __expf(m0 - mn0), al1 = __expf(m1 - mn1);
        m0 = mn0; m1 = mn1;

        float rs0 = 0.f, rs1 = 0.f;
        #pragma unroll
        for (int j = 0; j < 8; j++) {
            float s0 = sf[j][0], s1 = sf[j][1], s2 = sf[j][2], s3 = sf[j][3];
            float p0 = (s0 > -1e29f) ? __expf(s0 - mn0) : 0.f;
            float p1 = (s1 > -1e29f) ? __expf(s1 - mn0) : 0.f;
            float p2 = (s2 > -1e29f) ? __expf(s2 - mn1) : 0.f;
            float p3 = (s3 > -1e29f) ? __expf(s3 - mn1) : 0.f;
            sf[j][0] = p0; sf[j][1] = p1; sf[j][2] = p2; sf[j][3] = p3;
            rs0 += p0 + p1; rs1 += p2 + p3;
        }
        rs0 += __shfl_xor_sync(0xffffffffu, rs0, 1);
        rs0 += __shfl_xor_sync(0xffffffffu, rs0, 2);
        rs1 += __shfl_xor_sync(0xffffffffu, rs1, 1);
        rs1 += __shfl_xor_sync(0xffffffffu, rs1, 2);
        l0 = l0*al0 + rs0;
        l1 = l1*al1 + rs1;
        #pragma unroll
        for (int j = 0; j < 8; j++) {
            o[j][0] *= al0; o[j][1] *= al0;
            o[j][2] *= al1; o[j][3] *= al1;
        }

        // PV: O += Ph*Vh + Ph*Vl + Pl*Vh  (P from registers)
        #pragma unroll
        for (int kc = 0; kc < 4; kc++) {
            float ra, rb;
            uint32_t ph[4], pl[4];
            ph[0] = pack_hi2(sf[2*kc][0],   sf[2*kc][1],   ra, rb); pl[0] = pack_bf2(ra, rb);
            ph[1] = pack_hi2(sf[2*kc][2],   sf[2*kc][3],   ra, rb); pl[1] = pack_bf2(ra, rb);
            ph[2] = pack_hi2(sf[2*kc+1][0], sf[2*kc+1][1], ra, rb); pl[2] = pack_bf2(ra, rb);
            ph[3] = pack_hi2(sf[2*kc+1][2], sf[2*kc+1][3], ra, rb); pl[3] = pack_bf2(ra, rb);
            #pragma unroll
            for (int j = 0; j < 4; j++) {
                uint32_t off = SW128((uint32_t)((j*16 + (lane & 15))*128 + kc*32 + (lane >> 4)*16));
                uint32_t rh[4], rl[4];
                ldmx4(rh, vst + off);
                ldmx4(rl, vst + 8192 + off);
                uint32_t bh0[2] = {rh[0], rh[2]}, bh1[2] = {rh[1], rh[3]};
                uint32_t bl0[2] = {rl[0], rl[2]}, bl1[2] = {rl[1], rl[3]};
                mma16816(o[2*j],   ph, bh0); mma16816(o[2*j+1], ph, bh1);
                mma16816(o[2*j],   ph, bl0); mma16816(o[2*j+1], ph, bl1);
                mma16816(o[2*j],   pl, bh0); mma16816(o[2*j+1], pl, bh1);
            }
        }

        __syncthreads();
        if (t + 2 < nt) { load_kv(t + 2, t & 1); cp_commit(); }
    }

    // epilogue: normalize + split write to Ao
    float i0 = 1.f / l0, i1 = 1.f / l1;
    long row0 = (long)(z >> 3)*512 + qbase + wid*16 + (lane >> 2);
    long row1 = row0 + 8;
    int colb = (z & 7)*64 + (lane & 3)*2;
    #pragma unroll
    for (int j = 0; j < 8; j++) {
        int c = colb + j*8;
        float v0 = o[j][0]*i0, v1 = o[j][1]*i0;
        float v2 = o[j][2]*i1, v3 = o[j][3]*i1;
        __nv_bfloat162 h, l;
        h.x = __float2bfloat16(v0); h.y = __float2bfloat16(v1);
        l.x = __float2bfloat16(v0 - __bfloat162float(h.x));
        l.y = __float2bfloat16(v1 - __bfloat162float(h.y));
        bf16* p0 = Ao + row0*1536 + c;
        *(__nv_bfloat162*)(p0)        = h;
        *(__nv_bfloat162*)(p0 + 512)  = h;
        *(__nv_bfloat162*)(p0 + 1024) = l;
        h.x = __float2bfloat16(v2); h.y = __float2bfloat16(v3);
        l.x = __float2bfloat16(v2 - __bfloat162float(h.x));
        l.y = __float2bfloat16(v3 - __bfloat162float(h.y));
        bf16* p1 = Ao + row1*1536 + c;
        *(__nv_bfloat162*)(p1)        = h;
        *(__nv_bfloat162*)(p1 + 512)  = h;
        *(__nv_bfloat162*)(p1 + 1024) = l;
    }
}

// ---------------- pack kernels ----------------
__global__ void pack_BT(const float* __restrict__ src, bf16* __restrict__ out,
                        int rows, int cols, int ld, long s1, long s2, int zdiv)
{
    __shared__ float t[32][33];
    long z = blockIdx.z;
    const float* s = src + (z/zdiv)*s1 + (z%zdiv)*s2;
    int k0 = blockIdx.x*32, n0 = blockIdx.y*32;
    int tx = threadIdx.x, ty = threadIdx.y;
    #pragma unroll
    for (int i = 0; i < 32; i += 8)
        t[ty+i][tx] = s[(long)(k0+ty+i)*ld + n0 + tx];
    __syncthreads();
    const long K3 = 3L*rows;
    #pragma unroll
    for (int i = 0; i < 32; i += 8) {
        float v = t[tx][ty+i];
        bf16 hi, lo; split2(v, hi, lo);
        long nrow = z*(long)cols + n0 + ty + i;
        long ob = nrow*K3 + k0 + tx;
        out[ob] = hi; out[ob + rows] = lo; out[ob + 2L*rows] = hi;
    }
}

__global__ void pack_qk(const float* __restrict__ qsrc, int qld, int qoff,
                        const float* __restrict__ ksrc, int kld, int koff,
                        bf16* __restrict__ Aq, bf16* __restrict__ Bk)
{
    long idx = (long)blockIdx.x*256 + threadIdx.x;
    if (idx >= (long)64*512*64) return;
    int kk = (int)(idx & 63);
    int s  = (int)((idx >> 6) & 511);
    int z  = (int)(idx >> 15);
    int b = z >> 3, h = z & 7;
    long srow = (long)(b*512 + s);
    float qv = qsrc[srow*qld + qoff + h*64 + kk] * 0.125f;
    float kv = ksrc[srow*kld + koff + h*64 + kk];
    long ob = ((long)z*512 + s)*192;
    bf16 hi, lo;
    split2(qv, hi, lo); Aq[ob+kk] = hi; Aq[ob+64+kk] = hi; Aq[ob+128+kk] = lo;
    split2(kv, hi, lo); Bk[ob+kk] = hi; Bk[ob+64+kk] = lo; Bk[ob+128+kk] = hi;
}

// ---------------- elementwise ----------------
__global__ void add_ln2(const float* __restrict__ x, const float* __restrict__ a,
                        const float* __restrict__ g, const float* __restrict__ b,
                        float* __restrict__ out, bf16* __restrict__ As)
{
    long row = blockIdx.x;
    int tid = threadIdx.x;
    const float* xr = x + row*DD;
    const float* ar = a + row*DD;
    float v0 = xr[tid]     + ar[tid];
    float v1 = xr[tid+256] + ar[tid+256];
    __shared__ float red[256];
    red[tid] = v0 + v1; __syncthreads();
    for (int s = 128; s > 0; s >>= 1) { if (tid < s) red[tid] += red[tid+s]; __syncthreads(); }
    float mean = red[0]*(1.f/DD);
    __syncthreads();
    red[tid] = v0*v0 + v1*v1; __syncthreads();
    for (int s = 128; s > 0; s >>= 1) { if (tid < s) red[tid] += red[tid+s]; __syncthreads(); }
    float var = red[0]*(1.f/DD) - mean*mean;
    float rs = rsqrtf(var + 1e-5f);
    float o0 = (v0-mean)*rs*g[tid]     + b[tid];
    float o1 = (v1-mean)*rs*g[tid+256] + b[tid+256];
    out[row*DD + tid]     = o0;
    out[row*DD + tid+256] = o1;
    long ob = row*1536;
    bf16 hi, lo;
    split2(o0, hi, lo); As[ob+tid]     = hi; As[ob+512+tid]     = hi; As[ob+1024+tid]     = lo;
    split2(o1, hi, lo); As[ob+tid+256] = hi; As[ob+512+tid+256] = hi; As[ob+1024+tid+256] = lo;
}

__global__ void pe_kernel(float* __restrict__ pe)
{
    int idx = blockIdx.x*blockDim.x + threadIdx.x;
    if (idx >= SS_*DD) return;
    int d = idx & (DD-1);
    int s = idx >> 9;
    int i = d >> 1;
    double denom = exp(-log(10000.0) * (double)i / 256.0);
    double ang = (double)s * denom;
    pe[idx] = (d & 1) ? (float)cos(ang) : (float)sin(ang);
}

__global__ void add_pe2(const float* __restrict__ src, const float* __restrict__ pe,
                        float* __restrict__ out, bf16* __restrict__ As)
{
    int idx = blockIdx.x*blockDim.x + threadIdx.x;
    if (idx >= MS*DD) return;
    float v = src[idx] + pe[idx & (SS_*DD - 1)];
    out[idx] = v;
    int c = idx & 511;
    long row = idx >> 9;
    long ob = row*1536;
    bf16 hi, lo; split2(v, hi, lo);
    As[ob+c] = hi; As[ob+512+c] = hi; As[ob+1024+c] = lo;
}

// ---------------- host ----------------
static float *px, *py, *pqkv, *pa, *ppe;
static bf16  *pW, *pAx, *pAe, *pAff, *pAo, *pAq, *pBk, *pBv;

#define SM128 (3*(128*128 + 128*128) + 1024)
#define SM256 (3*(128*128 + 256*128) + 1024)
#define SMFLASH (49152 + 49152 + 32768 + 1024)

#define SZ_QKV (1536L*1536)
#define SZ_WO  (512L*1536)
#define SZ_W1  (2048L*1536)
#define SZ_W2  (512L*6144)
#define SZ_QW  (512L*1536)
#define SZ_KVW (1024L*1536)
#define L_ENC  (SZ_QKV + SZ_WO + SZ_W1 + SZ_W2)
#define L_DEC  (SZ_QKV + SZ_WO + SZ_QW + SZ_KVW + SZ_WO + SZ_W1 + SZ_W2)
#define DEC_BASE (6*L_ENC)

static void get_ptrs()
{
    if (px) return;
    cudaGetSymbolAddress((void**)&px,  g_x);
    cudaGetSymbolAddress((void**)&py,  g_y);
    cudaGetSymbolAddress((void**)&pqkv,g_qkv);
    cudaGetSymbolAddress((void**)&pa,  g_a);
    cudaGetSymbolAddress((void**)&ppe, g_pe);
    cudaGetSymbolAddress((void**)&pW,  g_W);
    cudaGetSymbolAddress((void**)&pAx, g_Ax);
    cudaGetSymbolAddress((void**)&pAe, g_Ae);
    cudaGetSymbolAddress((void**)&pAff,g_Aff);
    cudaGetSymbolAddress((void**)&pAo, g_Ao);
    cudaGetSymbolAddress((void**)&pAq, g_Aq);
    cudaGetSymbolAddress((void**)&pBk, g_Bk);
    cudaGetSymbolAddress((void**)&pBv, g_Bv);
    cudaFuncSetAttribute(gemm_mma<128,64,32>, cudaFuncAttributeMaxDynamicSharedMemorySize, SM128);
    cudaFuncSetAttribute(gemm_mma<256,64,64>, cudaFuncAttributeMaxDynamicSharedMemorySize, SM256);
    cudaFuncSetAttribute(flash_attn, cudaFuncAttributeMaxDynamicSharedMemorySize, SMFLASH);
}

static void gemmN(const bf16* A, const bf16* B, float* C, const float* bias,
                  bf16* Cs, int nreg, int M, int N, int Kp, int ldc, int relu)
{
    if (N >= 1024) {
        dim3 grid(N/256, M/128, 1);
        gemm_mma<256,64,64><<<grid,256,SM256>>>(A,B,C,bias,Cs,nreg,Kp,ldc,relu);
    } else {
        dim3 grid(N/128, M/128, 1);
        gemm_mma<128,64,32><<<grid,256,SM128>>>(A,B,C,bias,Cs,nreg,Kp,ldc,relu);
    }
}

// attention core: Q/K/V fp32 in pqkv; writes pre-LN attn result to g_a.
static void attn_core(int qld, const float* kvsrc, int kvld,
                      const bf16* Wo, const float* bo, int causal)
{
    pack_qk<<<(int)(((long)64*512*64+255)/256),256>>>(pqkv, qld, 0, kvsrc, kvld, 0, pAq, pBk);
    pack_BT<<<dim3(16,2,64),dim3(32,8)>>>(kvsrc + 512, pBv, 512, 64, kvld,
                                          (long)512*kvld, 64, 8);
    flash_attn<<<dim3(4,64),256,SMFLASH>>>(pAq, pBk, pBv, pAo, causal);
    gemmN(pAo, Wo, pa, bo, nullptr, 0, MS, 512, 1536, 512, 0);
}

extern "C" void kernel_launch(void* const* d_in, const int* in_sizes, int n_in,
                              void* d_out, int out_size)
{
    const float* src  = (const float*)d_in[0];
    const float* tgt  = (const float*)d_in[1];
    const float* eaw  = (const float*)d_in[2];
    const float* eab  = (const float*)d_in[3];
    const float* ewo  = (const float*)d_in[4];
    const float* ebo  = (const float*)d_in[5];
    const float* elg  = (const float*)d_in[6];
    const float* elb  = (const float*)d_in[7];
    const float* efw1 = (const float*)d_in[8];
    const float* efb1 = (const float*)d_in[9];
    const float* efw2 = (const float*)d_in[10];
    const float* efb2 = (const float*)d_in[11];
    const float* daw  = (const float*)d_in[12];
    const float* dab  = (const float*)d_in[13];
    const float* dwo  = (const float*)d_in[14];
    const float* dbo  = (const float*)d_in[15];
    const float* dlg  = (const float*)d_in[16];
    const float* dlb  = (const float*)d_in[17];
    const float* dfw1 = (const float*)d_in[18];
    const float* dfb1 = (const float*)d_in[19];
    const float* dfw2 = (const float*)d_in[20];
    const float* dfb2 = (const float*)d_in[21];
    float* out = (float*)d_out;

    get_ptrs();

    const long WATT = (long)3*HH*DD*DKK;
    const long WO_S = (long)HD*DD;

    // -------- pre-pack all weights --------
    for (int l = 0; l < LL; l++) {
        bf16* base = pW + (long)l*L_ENC;
        pack_BT<<<dim3(16,2,24),dim3(32,8)>>>(eaw + (long)l*WATT, base, 512, 64, 64,
                                              (long)512*64, 0, 1);
        pack_BT<<<dim3(16,16,1),dim3(32,8)>>>(ewo + (long)l*WO_S, base + SZ_QKV,
                                              512, 512, 512, 0, 0, 1);
        pack_BT<<<dim3(16,64,1),dim3(32,8)>>>(efw1 + (long)l*DD*DFFN, base + SZ_QKV + SZ_WO,
                                              512, 2048, 2048, 0, 0, 1);
        pack_BT<<<dim3(64,16,1),dim3(32,8)>>>(efw2 + (long)l*DFFN*DD,
                                              base + SZ_QKV + SZ_WO + SZ_W1,
                                              2048, 512, 512, 0, 0, 1);
    }
    for (int l = 0; l < LL; l++) {
        bf16* base = pW + DEC_BASE + (long)l*L_DEC;
        pack_BT<<<dim3(16,2,24),dim3(32,8)>>>(daw + (long)(l*2)*WATT, base, 512, 64, 64,
                                              (long)512*64, 0, 1);
        pack_BT<<<dim3(16,16,1),dim3(32,8)>>>(dwo + (long)(l*2)*WO_S, base + SZ_QKV,
                                              512, 512, 512, 0, 0, 1);
        pack_BT<<<dim3(16,2,8),dim3(32,8)>>>(daw + (long)(l*2+1)*WATT,
                                             base + SZ_QKV + SZ_WO, 512, 64, 64,
                                             (long)512*64, 0, 1);
        pack_BT<<<dim3(16,2,16),dim3(32,8)>>>(daw + (long)(l*2+1)*WATT + (long)8*512*64,
                                              base + SZ_QKV + SZ_WO + SZ_QW, 512, 64, 64,
                                              (long)512*64, 0, 1);
        pack_BT<<<dim3(16,16,1),dim3(32,8)>>>(dwo + (long)(l*2+1)*WO_S,
                                              base + SZ_QKV + SZ_WO + SZ_QW + SZ_KVW,
                                              512, 512, 512, 0, 0, 1);
        pack_BT<<<dim3(16,64,1),dim3(32,8)>>>(dfw1 + (long)l*DD*DFFN,
                                              base + SZ_QKV + 2*SZ_WO + SZ_QW + SZ_KVW,
                                              512, 2048, 2048, 0, 0, 1);
        pack_BT<<<dim3(64,16,1),dim3(32,8)>>>(dfw2 + (long)l*DFFN*DD,
                                              base + SZ_QKV + 2*SZ_WO + SZ_QW + SZ_KVW + SZ_W1,
                                              2048, 512, 512, 0, 0, 1);
    }

    pe_kernel<<<(SS_*DD+255)/256,256>>>(ppe);
    add_pe2<<<(MS*DD+255)/256,256>>>(src, ppe, px, pAx);

    // -------- encoder --------
    for (int l = 0; l < LL; l++) {
        bf16* base = pW + (long)l*L_ENC;
        gemmN(pAx, base, pqkv, eab + (long)l*1536, nullptr, 0, MS, 1536, 1536, 1536, 0);
        attn_core(1536, pqkv + 512, 1536, base + SZ_QKV, ebo + (long)l*DD, 0);
        add_ln2<<<MS,256>>>(px, pa, elg + (long)l*2*DD, elb + (long)l*2*DD, px, pAx);
        gemmN(pAx, base + SZ_QKV + SZ_WO, nullptr, efb1 + (long)l*DFFN, pAff, 2048,
              MS, 2048, 1536, 2048, 1);
        gemmN(pAff, base + SZ_QKV + SZ_WO + SZ_W1, pa, efb2 + (long)l*DD, nullptr, 0,
              MS, 512, 6144, 512, 0);
        bf16* As2 = (l == LL-1) ? pAe : pAx;
        add_ln2<<<MS,256>>>(px, pa, elg + (long)l*2*DD + DD, elb + (long)l*2*DD + DD, px, As2);
    }

    // -------- decoder --------
    add_pe2<<<(MS*DD+255)/256,256>>>(tgt, ppe, py, pAx);

    for (int l = 0; l < LL; l++) {
        bf16* base = pW + DEC_BASE + (long)l*L_DEC;
        // masked self-attention
        gemmN(pAx, base, pqkv, dab + (long)(l*2)*1536, nullptr, 0, MS, 1536, 1536, 1536, 0);
        attn_core(1536, pqkv + 512, 1536, base + SZ_QKV, dbo + (long)(l*2)*DD, 1);
        add_ln2<<<MS,256>>>(py, pa, dlg + (long)l*3*DD, dlb + (long)l*3*DD, py, pAx);
        // cross-attention
        gemmN(pAx, base + SZ_QKV + SZ_WO, pqkv, dab + (long)(l*2+1)*1536, nullptr, 0,
              MS, 512, 1536, 512, 0);
        gemmN(pAe, base + SZ_QKV + SZ_WO + SZ_QW, pqkv + (long)MS*512,
              dab + (long)(l*2+1)*1536 + 512, nullptr, 0, MS, 1024, 1536, 1024, 0);
        attn_core(512, pqkv + (long)MS*512, 1024,
                  base + SZ_QKV + SZ_WO + SZ_QW + SZ_KVW, dbo + (long)(l*2+1)*DD, 0);
        add_ln2<<<MS,256>>>(py, pa, dlg + (long)l*3*DD + DD, dlb + (long)l*3*DD + DD, py, pAx);
        // feed-forward
        gemmN(pAx, base + SZ_QKV + 2*SZ_WO + SZ_QW + SZ_KVW, nullptr,
              dfb1 + (long)l*DFFN, pAff, 2048, MS, 2048, 1536, 2048, 1);
        gemmN(pAff, base + SZ_QKV + 2*SZ_WO + SZ_QW + SZ_KVW + SZ_W1, pa,
              dfb2 + (long)l*DD, nullptr, 0, MS, 512, 6144, 512, 0);
        float* yo = (l == LL-1) ? out : py;
        add_ln2<<<MS,256>>>(py, pa, dlg + (long)l*3*DD + 2*DD, dlb + (long)l*3*DD + 2*DD, yo, pAx);
    }
}